// round 10
// baseline (speedup 1.0000x reference)
#include <cuda_runtime.h>
#include <cuda_bf16.h>
#include <mma.h>
#include <math.h>
#include <cstdint>

using namespace nvcuda;

#define L 1024
#define D 768
#define NH 12
#define HD 64
#define LH (L*NH)

// ---------------- scratch (device globals; no allocation allowed) ----------
__device__ float g_q[L*D];
__device__ float g_k[L*D];
__device__ float g_v[L*D];
__device__ float g_u[L*D];
__device__ float g_usum[L*D];
__device__ float g_ct[4*D];       // per-chunk totals
__device__ float g_gatep[L*128];  // padded gate output (128-wide)
__device__ float g_s[LH];
__device__ float g_es[LH];
__device__ float g_al[LH];
__device__ float g_be[LH];
__device__ float g_ga[LH];

// split-bf16 buffers
__device__ __nv_bfloat16 g_Xh[L*D];
__device__ __nv_bfloat16 g_Xl[L*D];
__device__ __nv_bfloat16 g_Wh[5*D*D];    // Wq,Wk,Wv,Wu,Wo
__device__ __nv_bfloat16 g_Wl[5*D*D];
__device__ __nv_bfloat16 g_Wgph[128*D];  // Wg padded to 128 rows (zero-init)
__device__ __nv_bfloat16 g_Wgpl[128*D];
__device__ __nv_bfloat16 g_lnh[L*D];
__device__ __nv_bfloat16 g_lnl[L*D];
__device__ __nv_bfloat16 g_qh[L*D];
__device__ __nv_bfloat16 g_ql[L*D];
__device__ __nv_bfloat16 g_kh[L*D];
__device__ __nv_bfloat16 g_kl[L*D];
__device__ __nv_bfloat16 g_vh[L*D];
__device__ __nv_bfloat16 g_vl[L*D];

// ---------------- fp32 -> (hi, lo) bf16 conversion --------------------------
__global__ void convert_inputs(const float* __restrict__ X,
                               const float* __restrict__ Wq,
                               const float* __restrict__ Wk,
                               const float* __restrict__ Wv,
                               const float* __restrict__ Wu,
                               const float* __restrict__ Wo,
                               const float* __restrict__ Wg) {
    int z = blockIdx.y;
    const float* src;
    __nv_bfloat16 *dh, *dl;
    int n;
    if (z == 0) { src = X; dh = g_Xh; dl = g_Xl; n = L * D; }
    else if (z <= 5) {
        const float* ws[5] = {Wq, Wk, Wv, Wu, Wo};
        src = ws[z - 1];
        dh = g_Wh + (size_t)(z - 1) * D * D;
        dl = g_Wl + (size_t)(z - 1) * D * D;
        n = D * D;
    } else {
        src = Wg; dh = g_Wgph; dl = g_Wgpl; n = 36 * D;  // rows 36..127 stay 0
    }
    for (int i = blockIdx.x * blockDim.x + threadIdx.x; i < n;
         i += gridDim.x * blockDim.x) {
        float v = src[i];
        __nv_bfloat16 h = __float2bfloat16(v);
        dh[i] = h;
        dl[i] = __float2bfloat16(v - __bfloat162float(h));
    }
}

// ---------------- cp.async helpers ------------------------------------------
__device__ __forceinline__ void cp16(void* dst, const void* src) {
    unsigned d = (unsigned)__cvta_generic_to_shared(dst);
    asm volatile("cp.async.cg.shared.global [%0], [%1], 16;" :: "r"(d), "l"(src));
}

// ---------------- split-bf16 tensor-core GEMM (128x128 tile, 3-stage) -------
// C[*,N] tile = A * B^T via 3 segment passes (Ah*Bh + Al*Bh + Ah*Bl).
// 8 warps, each owns 32x64 (2x4 fragments): 6 frag loads feed 8 mmas/k-step.
#define GBM 128
#define GBN 128
#define GBK 64
#define GLD 72
#define GSTAGE 3
#define GEMM_SMEM ((GBM + GBN) * GLD * 2 * GSTAGE)   // 110592 bytes

__device__ __forceinline__ void gemm_stage_load(
    __nv_bfloat16* As, __nv_bfloat16* Bs,
    const __nv_bfloat16* __restrict__ A, const __nv_bfloat16* __restrict__ B,
    int m0, int n0, int kt, int tid) {
#pragma unroll
    for (int i = 0; i < 4; i++) {
        int idx = tid + i * 256;
        int r = idx >> 3, c8 = (idx & 7) * 8;
        cp16(&As[r * GLD + c8], &A[(size_t)(m0 + r) * D + kt + c8]);
    }
#pragma unroll
    for (int i = 0; i < 4; i++) {
        int idx = tid + i * 256;
        int r = idx >> 3, c8 = (idx & 7) * 8;
        cp16(&Bs[r * GLD + c8], &B[(size_t)(n0 + r) * D + kt + c8]);
    }
    asm volatile("cp.async.commit_group;");
}

__device__ __forceinline__ void gemm_body(
    const __nv_bfloat16* __restrict__ Ah, const __nv_bfloat16* __restrict__ Al,
    const __nv_bfloat16* __restrict__ Bh, const __nv_bfloat16* __restrict__ Bl,
    float* __restrict__ C, int m0, int n0, int Cld, int cn0) {
    extern __shared__ __nv_bfloat16 sh[];
    const int tid = threadIdx.x;
    const int warp = tid >> 5;
    const int wm = warp >> 1, wn = warp & 1;   // wm 0..3 (32 rows), wn 0..1 (64 cols)

    wmma::fragment<wmma::accumulator, 16, 16, 16, float> acc[2][4];
#pragma unroll
    for (int i = 0; i < 2; i++)
#pragma unroll
        for (int j = 0; j < 4; j++) wmma::fill_fragment(acc[i][j], 0.f);

    const int NIT = 36;  // 3 segments x 12 k-tiles
    auto stA = [&](int s) { return sh + (size_t)s * (GBM + GBN) * GLD; };
    auto stB = [&](int s) { return sh + (size_t)s * (GBM + GBN) * GLD + GBM * GLD; };
    auto getAB = [&](int it, const __nv_bfloat16*& A, const __nv_bfloat16*& B,
                     int& kt) {
        int seg = it / 12;
        kt = (it % 12) * GBK;
        A = (seg == 1) ? Al : Ah;
        B = (seg == 2) ? Bl : Bh;
    };

    {
        const __nv_bfloat16 *A, *B;
        int kt;
        getAB(0, A, B, kt);
        gemm_stage_load(stA(0), stB(0), A, B, m0, n0, kt, tid);
        getAB(1, A, B, kt);
        gemm_stage_load(stA(1), stB(1), A, B, m0, n0, kt, tid);
    }

#pragma unroll 1
    for (int it = 0; it < NIT; it++) {
        if (it < NIT - 1) asm volatile("cp.async.wait_group 1;");
        else              asm volatile("cp.async.wait_group 0;");
        __syncthreads();

        const __nv_bfloat16* As = stA(it % GSTAGE);
        const __nv_bfloat16* Bs = stB(it % GSTAGE);
#pragma unroll
        for (int kk = 0; kk < GBK; kk += 16) {
            wmma::fragment<wmma::matrix_a, 16, 16, 16, __nv_bfloat16,
                           wmma::row_major> a0, a1;
            wmma::load_matrix_sync(a0, &As[(wm * 32) * GLD + kk], GLD);
            wmma::load_matrix_sync(a1, &As[(wm * 32 + 16) * GLD + kk], GLD);
#pragma unroll
            for (int j = 0; j < 4; j++) {
                wmma::fragment<wmma::matrix_b, 16, 16, 16, __nv_bfloat16,
                               wmma::col_major> bf;
                wmma::load_matrix_sync(bf, &Bs[(wn * 64 + j * 16) * GLD + kk],
                                       GLD);
                wmma::mma_sync(acc[0][j], a0, bf, acc[0][j]);
                wmma::mma_sync(acc[1][j], a1, bf, acc[1][j]);
            }
        }

        if (it + 2 < NIT) {
            const __nv_bfloat16 *A, *B;
            int kt;
            getAB(it + 2, A, B, kt);
            gemm_stage_load(stA((it + 2) % GSTAGE), stB((it + 2) % GSTAGE), A, B,
                            m0, n0, kt, tid);
        }
    }

#pragma unroll
    for (int i = 0; i < 2; i++)
#pragma unroll
        for (int j = 0; j < 4; j++)
            wmma::store_matrix_sync(
                &C[(size_t)(m0 + wm * 32 + i * 16) * Cld + cn0 + wn * 64 + j * 16],
                acc[i][j], Cld, wmma::mem_row_major);
}

// merged Q/K/V/U/gate projection: 24 qkvu n-blocks + 1 gate block
__global__ void __launch_bounds__(256) gemm_qkvu_tc() {
    int bx = blockIdx.x;
    int m0 = blockIdx.y * GBM;
    if (bx < 24) {
        int nglob = bx * GBN;
        int z = nglob / D;
        int n0 = nglob % D;
        float* Cs[4] = {g_q, g_k, g_v, g_u};
        gemm_body(g_Xh, g_Xl, g_Wh + (size_t)z * D * D, g_Wl + (size_t)z * D * D,
                  Cs[z], m0, n0, D, n0);
    } else {
        gemm_body(g_Xh, g_Xl, g_Wgph, g_Wgpl, g_gatep, m0, 0, 128, 0);
    }
}

__global__ void __launch_bounds__(256) gemm_out_tc(float* __restrict__ out) {
    int n0 = blockIdx.x * GBN;
    gemm_body(g_lnh, g_lnl, g_Wh + (size_t)4 * D * D, g_Wl + (size_t)4 * D * D,
              out, blockIdx.y * GBM, n0, D, n0);
}

// ---------------- fused: RoPE+normalize (split-emit)  ||  chunked cumsum ----
__device__ __forceinline__ void split_store(__nv_bfloat16* dh, __nv_bfloat16* dl,
                                            int idx, float v) {
    __nv_bfloat16 hb = __float2bfloat16(v);
    dh[idx] = hb;
    dl[idx] = __float2bfloat16(v - __bfloat162float(hb));
}

#define ROPE_BLOCKS 1536   // LH warps / 8 warps per block
#define CUMSUM_BLOCKS 384  // (D/8) channel-groups x 4 chunks

__global__ void __launch_bounds__(256) rope_cumsum_fused() {
    __shared__ float sm[32][9];
    const int bx = blockIdx.x;
    const int tid = threadIdx.x;

    if (bx < ROPE_BLOCKS) {
        // ---- RoPE + L2 norm path ----
        int gw = bx * 8 + (tid >> 5);
        int lane = tid & 31;
        int l = gw / NH, h = gw % NH;
        int base = l * D + h * HD;
        int i0 = lane >> 1;
        const float LN1E4_32 = 0.28782313662425572f;
        float f0 = expf(-(float)i0 * LN1E4_32);
        float f1 = expf(-(float)(i0 + 16) * LN1E4_32);
        float a0 = (float)l * f0;
        float a1 = (float)l * f1;
        float c0 = cosf(a0), sn0 = sinf(a0);
        float c1 = cosf(a1), sn1 = sinf(a1);

        {
            float x0 = g_q[base + lane], x1 = g_q[base + lane + 32];
            float r0 = x0 * c0 - x1 * sn0;
            float r1 = x1 * c1 + x0 * sn1;
            float nn = r0 * r0 + r1 * r1;
#pragma unroll
            for (int o = 16; o; o >>= 1) nn += __shfl_xor_sync(0xffffffffu, nn, o);
            float inv = 1.f / fmaxf(sqrtf(nn), 1e-12f);
            split_store(g_qh, g_ql, base + lane, r0 * inv);
            split_store(g_qh, g_ql, base + lane + 32, r1 * inv);
        }
        {
            float x0 = g_k[base + lane], x1 = g_k[base + lane + 32];
            float r0 = x0 * c0 - x1 * sn0;
            float r1 = x1 * c1 + x0 * sn1;
            float nn = r0 * r0 + r1 * r1;
#pragma unroll
            for (int o = 16; o; o >>= 1) nn += __shfl_xor_sync(0xffffffffu, nn, o);
            float inv = 1.f / fmaxf(sqrtf(nn), 1e-12f);
            split_store(g_kh, g_kl, base + lane, r0 * inv);
            split_store(g_kh, g_kl, base + lane + 32, r1 * inv);
        }
        {
            split_store(g_vh, g_vl, base + lane, g_v[base + lane]);
            split_store(g_vh, g_vl, base + lane + 32, g_v[base + lane + 32]);
        }
    } else {
        // ---- chunked cumsum path ----
        int bc = bx - ROPE_BLOCKS;
        const int c0 = (bc % 96) * 8;
        const int base = (bc / 96) * 256;
        const int w = tid >> 5, lane = tid & 31;
        const int lr = tid >> 3, lc = tid & 7;
        float carry = 0.f;
#pragma unroll 1
        for (int l0 = base; l0 < base + 256; l0 += 32) {
            float vin = g_u[(l0 + lr) * D + c0 + lc];
            __syncthreads();
            sm[lr][lc] = vin;
            __syncthreads();
            float v = sm[lane][w];
#pragma unroll
            for (int o = 1; o < 32; o <<= 1) {
                float n = __shfl_up_sync(0xffffffffu, v, o);
                if (lane >= o) v += n;
            }
            v += carry;
            carry = __shfl_sync(0xffffffffu, v, 31);
            sm[lane][w] = v;
            __syncthreads();
            g_usum[(l0 + lr) * D + c0 + lc] = sm[lr][lc];
        }
        if (lane == 0) g_ct[(bc / 96) * D + c0 + w] = carry;
    }
}

// ---------------- s_i = -(1/sqrt(d)) * u . bar_u (inline chunk prefix) ------
__global__ void compute_s(const float* __restrict__ pmu,
                          const float* __restrict__ plt) {
    int gw = (blockIdx.x * blockDim.x + threadIdx.x) >> 5;
    int lane = threadIdx.x & 31;
    if (gw >= LH) return;
    int l = gw / NH, h = gw % NH;
    float lt = expf(fminf(fmaxf(plt[h], -50.f), 30.f));
    float t = (float)(l + 1);
    float inv_den = 1.f / (lt + t);
    int chunk = l >> 8;
    float acc = 0.f;
#pragma unroll
    for (int r = 0; r < 2; r++) {
        int i = lane + r * 32;
        int ch = h * HD + i;
        float off = 0.f;
        for (int c = 0; c < chunk; c++) off += g_ct[c * D + ch];
        float uu = g_u[l * D + ch];
        float us = g_usum[l * D + ch] + off;
        float bu = (lt * pmu[ch] + us) * inv_den;
        acc = fmaf(uu, bu, acc);
    }
#pragma unroll
    for (int o = 16; o; o >>= 1) acc += __shfl_xor_sync(0xffffffffu, acc, o);
    if (lane == 0) g_s[l * NH + h] = -acc * 0.125f;
}

// ---------------- per-head: max, scans, gate coefficients -------------------
__global__ void __launch_bounds__(1024) head_scan() {
    __shared__ float she[1024];
    __shared__ float shp[1024];
    const int h = blockIdx.x;
    const int l = threadIdx.x;
    float s = g_s[l * NH + h];
    she[l] = s;
    __syncthreads();
    for (int off = 512; off > 0; off >>= 1) {
        if (l < off) she[l] = fmaxf(she[l], she[l + off]);
        __syncthreads();
    }
    float smax = she[0];
    __syncthreads();
    float e = expf(s - smax);
    float ev = e, pv = s;
    she[l] = ev;
    shp[l] = pv;
    __syncthreads();
    for (int off = 1; off < 1024; off <<= 1) {
        float ae = 0.f, ap = 0.f;
        if (l >= off) { ae = she[l - off]; ap = shp[l - off]; }
        __syncthreads();
        ev += ae;
        pv += ap;
        she[l] = ev;
        shp[l] = pv;
        __syncthreads();
    }
    float g1 = g_gatep[l * 128 + h * 3 + 0];
    float gh = g_gatep[l * 128 + h * 3 + 1];
    float s1 = 1.f / (1.f + expf(-g1));
    float shg = 1.f / (1.f + expf(-gh));
    float t = (float)(l + 1);
    float a = shg / (ev + 1e-12f);
    float b = (s1 - shg) / t;
    float gm = -(b * pv + shg) / t;
    int o = l * NH + h;
    g_es[o] = e;
    g_al[o] = a;
    g_be[o] = b;
    g_ga[o] = gm;
}

// ---------------- tensor-core weighted causal attention + LayerNorm ---------
#define ALD 72
#define SLD 68
#define ATTN_SMEM (8 * 64 * ALD * 2 + 64 * SLD * 4)

__global__ void __launch_bounds__(256) attn_tc() {
    extern __shared__ __nv_bfloat16 ash[];
    __nv_bfloat16* Qh = ash;
    __nv_bfloat16* Ql = ash + 1 * 64 * ALD;
    __nv_bfloat16* Kh = ash + 2 * 64 * ALD;
    __nv_bfloat16* Kl = ash + 3 * 64 * ALD;
    __nv_bfloat16* Vh = ash + 4 * 64 * ALD;
    __nv_bfloat16* Vl = ash + 5 * 64 * ALD;
    __nv_bfloat16* Sh = ash + 6 * 64 * ALD;
    __nv_bfloat16* Sl = ash + 7 * 64 * ALD;
    float* Sf = (float*)(ash + 8 * 64 * ALD);
    __shared__ float cA[64], cB[64], cG[64], sES[64], sS[64];

    const int h = blockIdx.y;
    const int lt = 15 - blockIdx.x;
    const int l0 = lt * 64;
    const int tid = threadIdx.x;
    const int warp = tid >> 5;
    const int wm = warp >> 1, wn = warp & 1;

#pragma unroll
    for (int it = 0; it < 2; it++) {
        int idx = tid + it * 256;
        int r = idx >> 3, c = (idx & 7) * 8;
        *(uint4*)&Qh[r * ALD + c] = *(const uint4*)&g_qh[(l0 + r) * D + h * HD + c];
        *(uint4*)&Ql[r * ALD + c] = *(const uint4*)&g_ql[(l0 + r) * D + h * HD + c];
    }
    if (tid < 64) {
        cA[tid] = g_al[(l0 + tid) * NH + h];
        cB[tid] = g_be[(l0 + tid) * NH + h];
        cG[tid] = g_ga[(l0 + tid) * NH + h];
    }

    wmma::fragment<wmma::accumulator, 16, 16, 16, float> acc_o[2];
    wmma::fill_fragment(acc_o[0], 0.f);
    wmma::fill_fragment(acc_o[1], 0.f);

    const int r_ = tid >> 2;
    const int cb_ = (tid & 3) * 16;

#pragma unroll 1
    for (int jt = 0; jt <= lt; jt++) {
        const int j0 = jt * 64;
        __syncthreads();
#pragma unroll
        for (int it = 0; it < 2; it++) {
            int idx = tid + it * 256;
            int r = idx >> 3, c = (idx & 7) * 8;
            *(uint4*)&Kh[r * ALD + c] = *(const uint4*)&g_kh[(j0 + r) * D + h * HD + c];
            *(uint4*)&Kl[r * ALD + c] = *(const uint4*)&g_kl[(j0 + r) * D + h * HD + c];
            *(uint4*)&Vh[r * ALD + c] = *(const uint4*)&g_vh[(j0 + r) * D + h * HD + c];
            *(uint4*)&Vl[r * ALD + c] = *(const uint4*)&g_vl[(j0 + r) * D + h * HD + c];
        }
        if (tid < 64) {
            sES[tid] = g_es[(j0 + tid) * NH + h];
            sS[tid] = g_s[(j0 + tid) * NH + h];
        }
        __syncthreads();

        wmma::fragment<wmma::accumulator, 16, 16, 16, float> acc_s[2];
        wmma::fill_fragment(acc_s[0], 0.f);
        wmma::fill_fragment(acc_s[1], 0.f);
#pragma unroll
        for (int p = 0; p < 3; p++) {
            const __nv_bfloat16* Aq = (p == 1) ? Ql : Qh;
            const __nv_bfloat16* Bk = (p == 2) ? Kl : Kh;
#pragma unroll
            for (int kk = 0; kk < 64; kk += 16) {
                wmma::fragment<wmma::matrix_a, 16, 16, 16, __nv_bfloat16,
                               wmma::row_major> af;
                wmma::load_matrix_sync(af, &Aq[(wm * 16) * ALD + kk], ALD);
#pragma unroll
                for (int jn = 0; jn < 2; jn++) {
                    wmma::fragment<wmma::matrix_b, 16, 16, 16, __nv_bfloat16,
                                   wmma::col_major> bf;
                    wmma::load_matrix_sync(
                        bf, &Bk[(wn * 32 + jn * 16) * ALD + kk], ALD);
                    wmma::mma_sync(acc_s[jn], af, bf, acc_s[jn]);
                }
            }
        }
#pragma unroll
        for (int jn = 0; jn < 2; jn++)
            wmma::store_matrix_sync(&Sf[(wm * 16) * SLD + wn * 32 + jn * 16],
                                    acc_s[jn], SLD, wmma::mem_row_major);
        __syncthreads();

        {
            float Ar = cA[r_], Br = cB[r_], Gr = cG[r_];
            int gl = l0 + r_;
#pragma unroll
            for (int i = 0; i < 16; i++) {
                int c = cb_ + i;
                float w = Ar * sES[c] + Br * sS[c] + Gr;
                float sv = (j0 + c <= gl) ? Sf[r_ * SLD + c] * w : 0.f;
                __nv_bfloat16 hb = __float2bfloat16(sv);
                Sh[r_ * ALD + c] = hb;
                Sl[r_ * ALD + c] = __float2bfloat16(sv - __bfloat162float(hb));
            }
        }
        __syncthreads();

#pragma unroll
        for (int p = 0; p < 3; p++) {
            const __nv_bfloat16* Asm = (p == 1) ? Sl : Sh;
            const __nv_bfloat16* Bvm = (p == 2) ? Vl : Vh;
#pragma unroll
            for (int kk = 0; kk < 64; kk += 16) {
                wmma::fragment<wmma::matrix_a, 16, 16, 16, __nv_bfloat16,
                               wmma::row_major> af;
                wmma::load_matrix_sync(af, &Asm[(wm * 16) * ALD + kk], ALD);
#pragma unroll
                for (int jn = 0; jn < 2; jn++) {
                    wmma::fragment<wmma::matrix_b, 16, 16, 16, __nv_bfloat16,
                                   wmma::row_major> bf;
                    wmma::load_matrix_sync(bf, &Bvm[kk * ALD + wn * 32 + jn * 16],
                                           ALD);
                    wmma::mma_sync(acc_o[jn], af, bf, acc_o[jn]);
                }
            }
        }
    }

    __syncthreads();
#pragma unroll
    for (int jn = 0; jn < 2; jn++)
        wmma::store_matrix_sync(&Sf[(wm * 16) * SLD + wn * 32 + jn * 16],
                                acc_o[jn], SLD, wmma::mem_row_major);
    __syncthreads();
    {
        float vals[16];
        float sum = 0.f;
#pragma unroll
        for (int i = 0; i < 16; i++) {
            vals[i] = Sf[r_ * SLD + cb_ + i];
            sum += vals[i];
        }
        sum += __shfl_xor_sync(0xffffffffu, sum, 1);
        sum += __shfl_xor_sync(0xffffffffu, sum, 2);
        float mean = sum * (1.f / 64.f);
        float vs = 0.f;
#pragma unroll
        for (int i = 0; i < 16; i++) {
            vals[i] -= mean;
            vs += vals[i] * vals[i];
        }
        vs += __shfl_xor_sync(0xffffffffu, vs, 1);
        vs += __shfl_xor_sync(0xffffffffu, vs, 2);
        float inv = rsqrtf(vs * (1.f / 64.f) + 1e-5f);
        int off = (l0 + r_) * D + h * HD + cb_;
#pragma unroll
        for (int i = 0; i < 16; i += 2) {
            float v0 = vals[i] * inv, v1 = vals[i + 1] * inv;
            __nv_bfloat16 h0 = __float2bfloat16(v0);
            __nv_bfloat16 h1 = __float2bfloat16(v1);
            *(__nv_bfloat162*)&g_lnh[off + i] = __nv_bfloat162(h0, h1);
            *(__nv_bfloat162*)&g_lnl[off + i] = __nv_bfloat162(
                __float2bfloat16(v0 - __bfloat162float(h0)),
                __float2bfloat16(v1 - __bfloat162float(h1)));
        }
    }
}

// ---------------- launch ----------------------------------------------------
extern "C" void kernel_launch(void* const* d_in, const int* in_sizes, int n_in,
                              void* d_out, int out_size) {
    const float* X = (const float*)d_in[0];
    const float* Wq = (const float*)d_in[1];
    const float* Wk = (const float*)d_in[2];
    const float* Wv = (const float*)d_in[3];
    const float* Wu = (const float*)d_in[4];
    const float* Wg = (const float*)d_in[5];
    const float* Wo = (const float*)d_in[6];
    const float* pmu = (const float*)d_in[7];
    const float* plt = (const float*)d_in[8];
    float* out = (float*)d_out;

    cudaFuncSetAttribute(attn_tc, cudaFuncAttributeMaxDynamicSharedMemorySize,
                         ATTN_SMEM);
    cudaFuncSetAttribute(gemm_qkvu_tc, cudaFuncAttributeMaxDynamicSharedMemorySize,
                         GEMM_SMEM);
    cudaFuncSetAttribute(gemm_out_tc, cudaFuncAttributeMaxDynamicSharedMemorySize,
                         GEMM_SMEM);

    convert_inputs<<<dim3(96, 7), 256>>>(X, Wq, Wk, Wv, Wu, Wo, Wg);

    // merged Q/K/V/U + gate projection (24 qkvu + 1 gate n-blocks x 8 m-blocks)
    gemm_qkvu_tc<<<dim3(25, L / GBM), 256, GEMM_SMEM>>>();

    // fused RoPE/normalize + chunked cumsum (independent, overlapped)
    rope_cumsum_fused<<<ROPE_BLOCKS + CUMSUM_BLOCKS, 256>>>();

    compute_s<<<(LH * 32 + 255) / 256, 256>>>(pmu, plt);
    head_scan<<<NH, 1024>>>();

    attn_tc<<<dim3(16, NH), 256, ATTN_SMEM>>>();

    gemm_out_tc<<<dim3(D / GBN, L / GBM), 256, GEMM_SMEM>>>(out);
}

// round 11
// speedup vs baseline: 1.5222x; 1.5222x over previous
#include <cuda_runtime.h>
#include <cuda_bf16.h>
#include <mma.h>
#include <math.h>
#include <cstdint>

using namespace nvcuda;

#define L 1024
#define D 768
#define NH 12
#define HD 64
#define LH (L*NH)

// ---------------- scratch (device globals; no allocation allowed) ----------
__device__ float g_q[L*D];
__device__ float g_k[L*D];
__device__ float g_v[L*D];
__device__ float g_u[L*D];
__device__ float g_usum[L*D];
__device__ float g_ct[4*D];      // per-chunk totals
__device__ float g_gatep[L*64];  // padded gate output (64-wide)
__device__ float g_s[LH];
__device__ float g_es[LH];
__device__ float g_al[LH];
__device__ float g_be[LH];
__device__ float g_ga[LH];

// split-bf16 buffers
__device__ __nv_bfloat16 g_Xh[L*D];
__device__ __nv_bfloat16 g_Xl[L*D];
__device__ __nv_bfloat16 g_Wh[5*D*D];   // Wq,Wk,Wv,Wu,Wo
__device__ __nv_bfloat16 g_Wl[5*D*D];
__device__ __nv_bfloat16 g_Wgph[64*D];  // Wg padded to 64 rows (zero-init)
__device__ __nv_bfloat16 g_Wgpl[64*D];
__device__ __nv_bfloat16 g_lnh[L*D];
__device__ __nv_bfloat16 g_lnl[L*D];
__device__ __nv_bfloat16 g_qh[L*D];
__device__ __nv_bfloat16 g_ql[L*D];
__device__ __nv_bfloat16 g_kh[L*D];
__device__ __nv_bfloat16 g_kl[L*D];
__device__ __nv_bfloat16 g_vh[L*D];
__device__ __nv_bfloat16 g_vl[L*D];

// ---------------- fp32 -> (hi, lo) bf16 conversion --------------------------
__global__ void convert_inputs(const float* __restrict__ X,
                               const float* __restrict__ Wq,
                               const float* __restrict__ Wk,
                               const float* __restrict__ Wv,
                               const float* __restrict__ Wu,
                               const float* __restrict__ Wo,
                               const float* __restrict__ Wg) {
    int z = blockIdx.y;
    const float* src;
    __nv_bfloat16 *dh, *dl;
    int n;
    if (z == 0) { src = X; dh = g_Xh; dl = g_Xl; n = L * D; }
    else if (z <= 5) {
        const float* ws[5] = {Wq, Wk, Wv, Wu, Wo};
        src = ws[z - 1];
        dh = g_Wh + (size_t)(z - 1) * D * D;
        dl = g_Wl + (size_t)(z - 1) * D * D;
        n = D * D;
    } else {
        src = Wg; dh = g_Wgph; dl = g_Wgpl; n = 36 * D;  // rows 36..63 stay 0
    }
    for (int i = blockIdx.x * blockDim.x + threadIdx.x; i < n;
         i += gridDim.x * blockDim.x) {
        float v = src[i];
        __nv_bfloat16 h = __float2bfloat16(v);
        dh[i] = h;
        dl[i] = __float2bfloat16(v - __bfloat162float(h));
    }
}

// ---------------- cp.async helpers ------------------------------------------
__device__ __forceinline__ void cp16(void* dst, const void* src) {
    unsigned d = (unsigned)__cvta_generic_to_shared(dst);
    asm volatile("cp.async.cg.shared.global [%0], [%1], 16;" :: "r"(d), "l"(src));
}

// ---------------- split-bf16 tensor-core GEMM (3-stage cp.async) ------------
// Proven R9 config: 128x64 tile, 8 warps, 2x2 frags.
#define GBM 128
#define GBN 64
#define GBK 64
#define GLD 72
#define GSTAGE 3
#define GEMM_SMEM ((GBM + GBN) * GLD * 2 * GSTAGE)   // 82944 bytes

__device__ __forceinline__ void gemm_stage_load(
    __nv_bfloat16* As, __nv_bfloat16* Bs,
    const __nv_bfloat16* __restrict__ A, const __nv_bfloat16* __restrict__ B,
    int m0, int n0, int kt, int tid) {
#pragma unroll
    for (int i = 0; i < 4; i++) {
        int idx = tid + i * 256;
        int r = idx >> 3, c8 = (idx & 7) * 8;
        cp16(&As[r * GLD + c8], &A[(size_t)(m0 + r) * D + kt + c8]);
    }
#pragma unroll
    for (int i = 0; i < 2; i++) {
        int idx = tid + i * 256;
        int r = idx >> 3, c8 = (idx & 7) * 8;
        cp16(&Bs[r * GLD + c8], &B[(size_t)(n0 + r) * D + kt + c8]);
    }
    asm volatile("cp.async.commit_group;");
}

__device__ __forceinline__ void gemm_body(
    const __nv_bfloat16* __restrict__ Ah, const __nv_bfloat16* __restrict__ Al,
    const __nv_bfloat16* __restrict__ Bh, const __nv_bfloat16* __restrict__ Bl,
    float* __restrict__ C, int m0, int n0, int Cld, int cn0) {
    extern __shared__ __nv_bfloat16 sh[];
    const int tid = threadIdx.x;
    const int warp = tid >> 5;
    const int wm = warp >> 1, wn = warp & 1;

    wmma::fragment<wmma::accumulator, 16, 16, 16, float> acc[2][2];
#pragma unroll
    for (int i = 0; i < 2; i++)
#pragma unroll
        for (int j = 0; j < 2; j++) wmma::fill_fragment(acc[i][j], 0.f);

    const int NIT = 36;  // 3 segments x 12 k-tiles
    auto stA = [&](int s) { return sh + (size_t)s * (GBM + GBN) * GLD; };
    auto stB = [&](int s) { return sh + (size_t)s * (GBM + GBN) * GLD + GBM * GLD; };
    auto getAB = [&](int it, const __nv_bfloat16*& A, const __nv_bfloat16*& B,
                     int& kt) {
        int seg = it / 12;
        kt = (it % 12) * GBK;
        A = (seg == 1) ? Al : Ah;
        B = (seg == 2) ? Bl : Bh;
    };

    {
        const __nv_bfloat16 *A, *B;
        int kt;
        getAB(0, A, B, kt);
        gemm_stage_load(stA(0), stB(0), A, B, m0, n0, kt, tid);
        getAB(1, A, B, kt);
        gemm_stage_load(stA(1), stB(1), A, B, m0, n0, kt, tid);
    }

#pragma unroll 1
    for (int it = 0; it < NIT; it++) {
        if (it < NIT - 1) asm volatile("cp.async.wait_group 1;");
        else              asm volatile("cp.async.wait_group 0;");
        __syncthreads();

        const __nv_bfloat16* As = stA(it % GSTAGE);
        const __nv_bfloat16* Bs = stB(it % GSTAGE);
#pragma unroll
        for (int kk = 0; kk < GBK; kk += 16) {
            wmma::fragment<wmma::matrix_a, 16, 16, 16, __nv_bfloat16,
                           wmma::row_major> a0, a1;
            wmma::fragment<wmma::matrix_b, 16, 16, 16, __nv_bfloat16,
                           wmma::col_major> b0, b1;
            wmma::load_matrix_sync(a0, &As[(wm * 32) * GLD + kk], GLD);
            wmma::load_matrix_sync(a1, &As[(wm * 32 + 16) * GLD + kk], GLD);
            wmma::load_matrix_sync(b0, &Bs[(wn * 32) * GLD + kk], GLD);
            wmma::load_matrix_sync(b1, &Bs[(wn * 32 + 16) * GLD + kk], GLD);
            wmma::mma_sync(acc[0][0], a0, b0, acc[0][0]);
            wmma::mma_sync(acc[0][1], a0, b1, acc[0][1]);
            wmma::mma_sync(acc[1][0], a1, b0, acc[1][0]);
            wmma::mma_sync(acc[1][1], a1, b1, acc[1][1]);
        }

        if (it + 2 < NIT) {
            const __nv_bfloat16 *A, *B;
            int kt;
            getAB(it + 2, A, B, kt);
            gemm_stage_load(stA((it + 2) % GSTAGE), stB((it + 2) % GSTAGE), A, B,
                            m0, n0, kt, tid);
        }
    }

#pragma unroll
    for (int i = 0; i < 2; i++)
#pragma unroll
        for (int j = 0; j < 2; j++)
            wmma::store_matrix_sync(
                &C[(size_t)(m0 + wm * 32 + i * 16) * Cld + cn0 + wn * 32 + j * 16],
                acc[i][j], Cld, wmma::mem_row_major);
}

// merged Q/K/V/U/gate projection: 49 n-blocks (48 qkvu + 1 gate)
__global__ void __launch_bounds__(256) gemm_qkvu_tc() {
    int bx = blockIdx.x;
    int m0 = blockIdx.y * GBM;
    if (bx < 48) {
        int nglob = bx * GBN;
        int z = nglob / D;
        int n0 = nglob % D;
        float* Cs[4] = {g_q, g_k, g_v, g_u};
        gemm_body(g_Xh, g_Xl, g_Wh + (size_t)z * D * D, g_Wl + (size_t)z * D * D,
                  Cs[z], m0, n0, D, n0);
    } else {
        gemm_body(g_Xh, g_Xl, g_Wgph, g_Wgpl, g_gatep, m0, 0, 64, 0);
    }
}

__global__ void __launch_bounds__(256) gemm_out_tc(float* __restrict__ out) {
    int n0 = blockIdx.x * GBN;
    gemm_body(g_lnh, g_lnl, g_Wh + (size_t)4 * D * D, g_Wl + (size_t)4 * D * D,
              out, blockIdx.y * GBM, n0, D, n0);
}

// ---------------- fused: RoPE+normalize (trig hoisted)  ||  chunked cumsum --
__device__ __forceinline__ void split_store(__nv_bfloat16* dh, __nv_bfloat16* dl,
                                            int idx, float v) {
    __nv_bfloat16 hb = __float2bfloat16(v);
    dh[idx] = hb;
    dl[idx] = __float2bfloat16(v - __bfloat162float(hb));
}

#define ROPE_BLOCKS 128    // L warps, 8 warps per block: warp = one position l
#define CUMSUM_BLOCKS 384  // (D/8) channel-groups x 4 chunks

__global__ void __launch_bounds__(256) rope_cumsum_fused() {
    __shared__ float sm[32][9];
    const int bx = blockIdx.x;
    const int tid = threadIdx.x;

    if (bx < ROPE_BLOCKS) {
        // ---- RoPE + L2 norm: warp per position l, loop over heads ----
        int l = bx * 8 + (tid >> 5);
        int lane = tid & 31;
        int i0 = lane >> 1;
        const float LN1E4_32 = 0.28782313662425572f;
        float f0 = expf(-(float)i0 * LN1E4_32);
        float f1 = expf(-(float)(i0 + 16) * LN1E4_32);
        float a0 = (float)l * f0;
        float a1 = (float)l * f1;
        float c0 = cosf(a0), sn0 = sinf(a0);
        float c1 = cosf(a1), sn1 = sinf(a1);

#pragma unroll 1
        for (int h = 0; h < NH; h++) {
            int base = l * D + h * HD;
            {
                float x0 = g_q[base + lane], x1 = g_q[base + lane + 32];
                float r0 = x0 * c0 - x1 * sn0;
                float r1 = x1 * c1 + x0 * sn1;
                float nn = r0 * r0 + r1 * r1;
#pragma unroll
                for (int o = 16; o; o >>= 1)
                    nn += __shfl_xor_sync(0xffffffffu, nn, o);
                float inv = 1.f / fmaxf(sqrtf(nn), 1e-12f);
                split_store(g_qh, g_ql, base + lane, r0 * inv);
                split_store(g_qh, g_ql, base + lane + 32, r1 * inv);
            }
            {
                float x0 = g_k[base + lane], x1 = g_k[base + lane + 32];
                float r0 = x0 * c0 - x1 * sn0;
                float r1 = x1 * c1 + x0 * sn1;
                float nn = r0 * r0 + r1 * r1;
#pragma unroll
                for (int o = 16; o; o >>= 1)
                    nn += __shfl_xor_sync(0xffffffffu, nn, o);
                float inv = 1.f / fmaxf(sqrtf(nn), 1e-12f);
                split_store(g_kh, g_kl, base + lane, r0 * inv);
                split_store(g_kh, g_kl, base + lane + 32, r1 * inv);
            }
            {
                split_store(g_vh, g_vl, base + lane, g_v[base + lane]);
                split_store(g_vh, g_vl, base + lane + 32, g_v[base + lane + 32]);
            }
        }
    } else {
        // ---- chunked cumsum path ----
        int bc = bx - ROPE_BLOCKS;
        const int c0 = (bc % 96) * 8;
        const int base = (bc / 96) * 256;
        const int w = tid >> 5, lane = tid & 31;
        const int lr = tid >> 3, lc = tid & 7;
        float carry = 0.f;
#pragma unroll 1
        for (int l0 = base; l0 < base + 256; l0 += 32) {
            float vin = g_u[(l0 + lr) * D + c0 + lc];
            __syncthreads();
            sm[lr][lc] = vin;
            __syncthreads();
            float v = sm[lane][w];
#pragma unroll
            for (int o = 1; o < 32; o <<= 1) {
                float n = __shfl_up_sync(0xffffffffu, v, o);
                if (lane >= o) v += n;
            }
            v += carry;
            carry = __shfl_sync(0xffffffffu, v, 31);
            sm[lane][w] = v;
            __syncthreads();
            g_usum[(l0 + lr) * D + c0 + lc] = sm[lr][lc];
        }
        if (lane == 0) g_ct[(bc / 96) * D + c0 + w] = carry;
    }
}

// ---------------- s_i = -(1/sqrt(d)) * u . bar_u (inline chunk prefix) ------
__global__ void compute_s(const float* __restrict__ pmu,
                          const float* __restrict__ plt) {
    int gw = (blockIdx.x * blockDim.x + threadIdx.x) >> 5;
    int lane = threadIdx.x & 31;
    if (gw >= LH) return;
    int l = gw / NH, h = gw % NH;
    float lt = expf(fminf(fmaxf(plt[h], -50.f), 30.f));
    float t = (float)(l + 1);
    float inv_den = 1.f / (lt + t);
    int chunk = l >> 8;
    float acc = 0.f;
#pragma unroll
    for (int r = 0; r < 2; r++) {
        int i = lane + r * 32;
        int ch = h * HD + i;
        float off = 0.f;
        for (int c = 0; c < chunk; c++) off += g_ct[c * D + ch];
        float uu = g_u[l * D + ch];
        float us = g_usum[l * D + ch] + off;
        float bu = (lt * pmu[ch] + us) * inv_den;
        acc = fmaf(uu, bu, acc);
    }
#pragma unroll
    for (int o = 16; o; o >>= 1) acc += __shfl_xor_sync(0xffffffffu, acc, o);
    if (lane == 0) g_s[l * NH + h] = -acc * 0.125f;
}

// ---------------- per-head: max, scans, gate coefficients -------------------
__global__ void __launch_bounds__(1024) head_scan() {
    __shared__ float she[1024];
    __shared__ float shp[1024];
    const int h = blockIdx.x;
    const int l = threadIdx.x;
    float s = g_s[l * NH + h];
    she[l] = s;
    __syncthreads();
    for (int off = 512; off > 0; off >>= 1) {
        if (l < off) she[l] = fmaxf(she[l], she[l + off]);
        __syncthreads();
    }
    float smax = she[0];
    __syncthreads();
    float e = expf(s - smax);
    float ev = e, pv = s;
    she[l] = ev;
    shp[l] = pv;
    __syncthreads();
    for (int off = 1; off < 1024; off <<= 1) {
        float ae = 0.f, ap = 0.f;
        if (l >= off) { ae = she[l - off]; ap = shp[l - off]; }
        __syncthreads();
        ev += ae;
        pv += ap;
        she[l] = ev;
        shp[l] = pv;
        __syncthreads();
    }
    float g1 = g_gatep[l * 64 + h * 3 + 0];
    float gh = g_gatep[l * 64 + h * 3 + 1];
    float s1 = 1.f / (1.f + expf(-g1));
    float shg = 1.f / (1.f + expf(-gh));
    float t = (float)(l + 1);
    float a = shg / (ev + 1e-12f);
    float b = (s1 - shg) / t;
    float gm = -(b * pv + shg) / t;
    int o = l * NH + h;
    g_es[o] = e;
    g_al[o] = a;
    g_be[o] = b;
    g_ga[o] = gm;
}

// ---------------- tensor-core weighted causal attention + LayerNorm ---------
#define ALD 72
#define SLD 68
#define ATTN_SMEM (8 * 64 * ALD * 2 + 64 * SLD * 4)

__global__ void __launch_bounds__(256) attn_tc() {
    extern __shared__ __nv_bfloat16 ash[];
    __nv_bfloat16* Qh = ash;
    __nv_bfloat16* Ql = ash + 1 * 64 * ALD;
    __nv_bfloat16* Kh = ash + 2 * 64 * ALD;
    __nv_bfloat16* Kl = ash + 3 * 64 * ALD;
    __nv_bfloat16* Vh = ash + 4 * 64 * ALD;
    __nv_bfloat16* Vl = ash + 5 * 64 * ALD;
    __nv_bfloat16* Sh = ash + 6 * 64 * ALD;
    __nv_bfloat16* Sl = ash + 7 * 64 * ALD;
    float* Sf = (float*)(ash + 8 * 64 * ALD);
    __shared__ float cA[64], cB[64], cG[64], sES[64], sS[64];

    const int h = blockIdx.y;
    const int lt = 15 - blockIdx.x;
    const int l0 = lt * 64;
    const int tid = threadIdx.x;
    const int warp = tid >> 5;
    const int wm = warp >> 1, wn = warp & 1;

#pragma unroll
    for (int it = 0; it < 2; it++) {
        int idx = tid + it * 256;
        int r = idx >> 3, c = (idx & 7) * 8;
        *(uint4*)&Qh[r * ALD + c] = *(const uint4*)&g_qh[(l0 + r) * D + h * HD + c];
        *(uint4*)&Ql[r * ALD + c] = *(const uint4*)&g_ql[(l0 + r) * D + h * HD + c];
    }
    if (tid < 64) {
        cA[tid] = g_al[(l0 + tid) * NH + h];
        cB[tid] = g_be[(l0 + tid) * NH + h];
        cG[tid] = g_ga[(l0 + tid) * NH + h];
    }

    wmma::fragment<wmma::accumulator, 16, 16, 16, float> acc_o[2];
    wmma::fill_fragment(acc_o[0], 0.f);
    wmma::fill_fragment(acc_o[1], 0.f);

    const int r_ = tid >> 2;
    const int cb_ = (tid & 3) * 16;

#pragma unroll 1
    for (int jt = 0; jt <= lt; jt++) {
        const int j0 = jt * 64;
        __syncthreads();
#pragma unroll
        for (int it = 0; it < 2; it++) {
            int idx = tid + it * 256;
            int r = idx >> 3, c = (idx & 7) * 8;
            *(uint4*)&Kh[r * ALD + c] = *(const uint4*)&g_kh[(j0 + r) * D + h * HD + c];
            *(uint4*)&Kl[r * ALD + c] = *(const uint4*)&g_kl[(j0 + r) * D + h * HD + c];
            *(uint4*)&Vh[r * ALD + c] = *(const uint4*)&g_vh[(j0 + r) * D + h * HD + c];
            *(uint4*)&Vl[r * ALD + c] = *(const uint4*)&g_vl[(j0 + r) * D + h * HD + c];
        }
        if (tid < 64) {
            sES[tid] = g_es[(j0 + tid) * NH + h];
            sS[tid] = g_s[(j0 + tid) * NH + h];
        }
        __syncthreads();

        wmma::fragment<wmma::accumulator, 16, 16, 16, float> acc_s[2];
        wmma::fill_fragment(acc_s[0], 0.f);
        wmma::fill_fragment(acc_s[1], 0.f);
#pragma unroll
        for (int p = 0; p < 3; p++) {
            const __nv_bfloat16* Aq = (p == 1) ? Ql : Qh;
            const __nv_bfloat16* Bk = (p == 2) ? Kl : Kh;
#pragma unroll
            for (int kk = 0; kk < 64; kk += 16) {
                wmma::fragment<wmma::matrix_a, 16, 16, 16, __nv_bfloat16,
                               wmma::row_major> af;
                wmma::load_matrix_sync(af, &Aq[(wm * 16) * ALD + kk], ALD);
#pragma unroll
                for (int jn = 0; jn < 2; jn++) {
                    wmma::fragment<wmma::matrix_b, 16, 16, 16, __nv_bfloat16,
                                   wmma::col_major> bf;
                    wmma::load_matrix_sync(
                        bf, &Bk[(wn * 32 + jn * 16) * ALD + kk], ALD);
                    wmma::mma_sync(acc_s[jn], af, bf, acc_s[jn]);
                }
            }
        }
#pragma unroll
        for (int jn = 0; jn < 2; jn++)
            wmma::store_matrix_sync(&Sf[(wm * 16) * SLD + wn * 32 + jn * 16],
                                    acc_s[jn], SLD, wmma::mem_row_major);
        __syncthreads();

        {
            float Ar = cA[r_], Br = cB[r_], Gr = cG[r_];
            int gl = l0 + r_;
#pragma unroll
            for (int i = 0; i < 16; i++) {
                int c = cb_ + i;
                float w = Ar * sES[c] + Br * sS[c] + Gr;
                float sv = (j0 + c <= gl) ? Sf[r_ * SLD + c] * w : 0.f;
                __nv_bfloat16 hb = __float2bfloat16(sv);
                Sh[r_ * ALD + c] = hb;
                Sl[r_ * ALD + c] = __float2bfloat16(sv - __bfloat162float(hb));
            }
        }
        __syncthreads();

#pragma unroll
        for (int p = 0; p < 3; p++) {
            const __nv_bfloat16* Asm = (p == 1) ? Sl : Sh;
            const __nv_bfloat16* Bvm = (p == 2) ? Vl : Vh;
#pragma unroll
            for (int kk = 0; kk < 64; kk += 16) {
                wmma::fragment<wmma::matrix_a, 16, 16, 16, __nv_bfloat16,
                               wmma::row_major> af;
                wmma::load_matrix_sync(af, &Asm[(wm * 16) * ALD + kk], ALD);
#pragma unroll
                for (int jn = 0; jn < 2; jn++) {
                    wmma::fragment<wmma::matrix_b, 16, 16, 16, __nv_bfloat16,
                                   wmma::row_major> bf;
                    wmma::load_matrix_sync(bf, &Bvm[kk * ALD + wn * 32 + jn * 16],
                                           ALD);
                    wmma::mma_sync(acc_o[jn], af, bf, acc_o[jn]);
                }
            }
        }
    }

    __syncthreads();
#pragma unroll
    for (int jn = 0; jn < 2; jn++)
        wmma::store_matrix_sync(&Sf[(wm * 16) * SLD + wn * 32 + jn * 16],
                                acc_o[jn], SLD, wmma::mem_row_major);
    __syncthreads();
    {
        float vals[16];
        float sum = 0.f;
#pragma unroll
        for (int i = 0; i < 16; i++) {
            vals[i] = Sf[r_ * SLD + cb_ + i];
            sum += vals[i];
        }
        sum += __shfl_xor_sync(0xffffffffu, sum, 1);
        sum += __shfl_xor_sync(0xffffffffu, sum, 2);
        float mean = sum * (1.f / 64.f);
        float vs = 0.f;
#pragma unroll
        for (int i = 0; i < 16; i++) {
            vals[i] -= mean;
            vs += vals[i] * vals[i];
        }
        vs += __shfl_xor_sync(0xffffffffu, vs, 1);
        vs += __shfl_xor_sync(0xffffffffu, vs, 2);
        float inv = rsqrtf(vs * (1.f / 64.f) + 1e-5f);
        int off = (l0 + r_) * D + h * HD + cb_;
#pragma unroll
        for (int i = 0; i < 16; i += 2) {
            float v0 = vals[i] * inv, v1 = vals[i + 1] * inv;
            __nv_bfloat16 h0 = __float2bfloat16(v0);
            __nv_bfloat16 h1 = __float2bfloat16(v1);
            *(__nv_bfloat162*)&g_lnh[off + i] = __nv_bfloat162(h0, h1);
            *(__nv_bfloat162*)&g_lnl[off + i] = __nv_bfloat162(
                __float2bfloat16(v0 - __bfloat162float(h0)),
                __float2bfloat16(v1 - __bfloat162float(h1)));
        }
    }
}

// ---------------- launch ----------------------------------------------------
extern "C" void kernel_launch(void* const* d_in, const int* in_sizes, int n_in,
                              void* d_out, int out_size) {
    const float* X = (const float*)d_in[0];
    const float* Wq = (const float*)d_in[1];
    const float* Wk = (const float*)d_in[2];
    const float* Wv = (const float*)d_in[3];
    const float* Wu = (const float*)d_in[4];
    const float* Wg = (const float*)d_in[5];
    const float* Wo = (const float*)d_in[6];
    const float* pmu = (const float*)d_in[7];
    const float* plt = (const float*)d_in[8];
    float* out = (float*)d_out;

    cudaFuncSetAttribute(attn_tc, cudaFuncAttributeMaxDynamicSharedMemorySize,
                         ATTN_SMEM);
    cudaFuncSetAttribute(gemm_qkvu_tc, cudaFuncAttributeMaxDynamicSharedMemorySize,
                         GEMM_SMEM);
    cudaFuncSetAttribute(gemm_out_tc, cudaFuncAttributeMaxDynamicSharedMemorySize,
                         GEMM_SMEM);

    convert_inputs<<<dim3(96, 7), 256>>>(X, Wq, Wk, Wv, Wu, Wo, Wg);

    // merged Q/K/V/U + gate projection (49 n-blocks x 8 m-blocks)
    gemm_qkvu_tc<<<dim3(49, L / GBM), 256, GEMM_SMEM>>>();

    // fused RoPE/normalize (trig hoisted) + chunked cumsum
    rope_cumsum_fused<<<ROPE_BLOCKS + CUMSUM_BLOCKS, 256>>>();

    compute_s<<<(LH * 32 + 255) / 256, 256>>>(pmu, plt);
    head_scan<<<NH, 1024>>>();

    attn_tc<<<dim3(16, NH), 256, ATTN_SMEM>>>();

    gemm_out_tc<<<dim3(D / GBN, L / GBM), 256, GEMM_SMEM>>>(out);
}

// round 12
// speedup vs baseline: 1.5964x; 1.0487x over previous
#include <cuda_runtime.h>
#include <cuda_bf16.h>
#include <mma.h>
#include <math.h>
#include <cstdint>

using namespace nvcuda;

#define L 1024
#define D 768
#define NH 12
#define HD 64
#define LH (L*NH)

// ---------------- scratch (device globals; no allocation allowed) ----------
__device__ float g_q[L*D];
__device__ float g_k[L*D];
__device__ float g_u[L*D];
__device__ float g_usum[L*D];
__device__ float g_ct[4*D];      // per-chunk totals
__device__ float g_gatep[L*64];  // padded gate output (64-wide)
__device__ float g_s[LH];
__device__ float g_es[LH];
__device__ float g_al[LH];
__device__ float g_be[LH];
__device__ float g_ga[LH];

// split-bf16 buffers
__device__ __nv_bfloat16 g_Xh[L*D];
__device__ __nv_bfloat16 g_Xl[L*D];
__device__ __nv_bfloat16 g_Wh[5*D*D];   // Wq,Wk,Wv,Wu,Wo
__device__ __nv_bfloat16 g_Wl[5*D*D];
__device__ __nv_bfloat16 g_Wgph[64*D];  // Wg padded to 64 rows (zero-init)
__device__ __nv_bfloat16 g_Wgpl[64*D];
__device__ __nv_bfloat16 g_lnh[L*D];
__device__ __nv_bfloat16 g_lnl[L*D];
__device__ __nv_bfloat16 g_qh[L*D];
__device__ __nv_bfloat16 g_ql[L*D];
__device__ __nv_bfloat16 g_kh[L*D];
__device__ __nv_bfloat16 g_kl[L*D];
__device__ __nv_bfloat16 g_vh[L*D];
__device__ __nv_bfloat16 g_vl[L*D];

// ---------------- fp32 -> (hi, lo) bf16 conversion --------------------------
__global__ void convert_inputs(const float* __restrict__ X,
                               const float* __restrict__ Wq,
                               const float* __restrict__ Wk,
                               const float* __restrict__ Wv,
                               const float* __restrict__ Wu,
                               const float* __restrict__ Wo,
                               const float* __restrict__ Wg) {
    int z = blockIdx.y;
    const float* src;
    __nv_bfloat16 *dh, *dl;
    int n;
    if (z == 0) { src = X; dh = g_Xh; dl = g_Xl; n = L * D; }
    else if (z <= 5) {
        const float* ws[5] = {Wq, Wk, Wv, Wu, Wo};
        src = ws[z - 1];
        dh = g_Wh + (size_t)(z - 1) * D * D;
        dl = g_Wl + (size_t)(z - 1) * D * D;
        n = D * D;
    } else {
        src = Wg; dh = g_Wgph; dl = g_Wgpl; n = 36 * D;  // rows 36..63 stay 0
    }
    for (int i = blockIdx.x * blockDim.x + threadIdx.x; i < n;
         i += gridDim.x * blockDim.x) {
        float v = src[i];
        __nv_bfloat16 h = __float2bfloat16(v);
        dh[i] = h;
        dl[i] = __float2bfloat16(v - __bfloat162float(h));
    }
}

// ---------------- cp.async helpers ------------------------------------------
__device__ __forceinline__ void cp16(void* dst, const void* src) {
    unsigned d = (unsigned)__cvta_generic_to_shared(dst);
    asm volatile("cp.async.cg.shared.global [%0], [%1], 16;" :: "r"(d), "l"(src));
}

__device__ __forceinline__ void split_store(__nv_bfloat16* dh, __nv_bfloat16* dl,
                                            int idx, float v) {
    __nv_bfloat16 hb = __float2bfloat16(v);
    dh[idx] = hb;
    dl[idx] = __float2bfloat16(v - __bfloat162float(hb));
}

// ---------------- split-bf16 tensor-core GEMM (3-stage cp.async) ------------
// Proven R9 config: 128x64 tile, 8 warps, 2x2 frags.
#define GBM 128
#define GBN 64
#define GBK 64
#define GLD 72
#define GSTAGE 3
#define GEMM_SMEM ((GBM + GBN) * GLD * 2 * GSTAGE)   // 82944 bytes

__device__ __forceinline__ void gemm_stage_load(
    __nv_bfloat16* As, __nv_bfloat16* Bs,
    const __nv_bfloat16* __restrict__ A, const __nv_bfloat16* __restrict__ B,
    int m0, int n0, int kt, int tid) {
#pragma unroll
    for (int i = 0; i < 4; i++) {
        int idx = tid + i * 256;
        int r = idx >> 3, c8 = (idx & 7) * 8;
        cp16(&As[r * GLD + c8], &A[(size_t)(m0 + r) * D + kt + c8]);
    }
#pragma unroll
    for (int i = 0; i < 2; i++) {
        int idx = tid + i * 256;
        int r = idx >> 3, c8 = (idx & 7) * 8;
        cp16(&Bs[r * GLD + c8], &B[(size_t)(n0 + r) * D + kt + c8]);
    }
    asm volatile("cp.async.commit_group;");
}

// If Ch != nullptr: split-bf16 epilogue (via smem round-trip) instead of fp32 C.
__device__ __forceinline__ void gemm_body(
    const __nv_bfloat16* __restrict__ Ah, const __nv_bfloat16* __restrict__ Al,
    const __nv_bfloat16* __restrict__ Bh, const __nv_bfloat16* __restrict__ Bl,
    float* __restrict__ C, int m0, int n0, int Cld, int cn0,
    __nv_bfloat16* Ch, __nv_bfloat16* Cl) {
    extern __shared__ __nv_bfloat16 sh[];
    const int tid = threadIdx.x;
    const int warp = tid >> 5;
    const int wm = warp >> 1, wn = warp & 1;

    wmma::fragment<wmma::accumulator, 16, 16, 16, float> acc[2][2];
#pragma unroll
    for (int i = 0; i < 2; i++)
#pragma unroll
        for (int j = 0; j < 2; j++) wmma::fill_fragment(acc[i][j], 0.f);

    const int NIT = 36;  // 3 segments x 12 k-tiles
    auto stA = [&](int s) { return sh + (size_t)s * (GBM + GBN) * GLD; };
    auto stB = [&](int s) { return sh + (size_t)s * (GBM + GBN) * GLD + GBM * GLD; };
    auto getAB = [&](int it, const __nv_bfloat16*& A, const __nv_bfloat16*& B,
                     int& kt) {
        int seg = it / 12;
        kt = (it % 12) * GBK;
        A = (seg == 1) ? Al : Ah;
        B = (seg == 2) ? Bl : Bh;
    };

    {
        const __nv_bfloat16 *A, *B;
        int kt;
        getAB(0, A, B, kt);
        gemm_stage_load(stA(0), stB(0), A, B, m0, n0, kt, tid);
        getAB(1, A, B, kt);
        gemm_stage_load(stA(1), stB(1), A, B, m0, n0, kt, tid);
    }

#pragma unroll 1
    for (int it = 0; it < NIT; it++) {
        if (it < NIT - 1) asm volatile("cp.async.wait_group 1;");
        else              asm volatile("cp.async.wait_group 0;");
        __syncthreads();

        const __nv_bfloat16* As = stA(it % GSTAGE);
        const __nv_bfloat16* Bs = stB(it % GSTAGE);
#pragma unroll
        for (int kk = 0; kk < GBK; kk += 16) {
            wmma::fragment<wmma::matrix_a, 16, 16, 16, __nv_bfloat16,
                           wmma::row_major> a0, a1;
            wmma::fragment<wmma::matrix_b, 16, 16, 16, __nv_bfloat16,
                           wmma::col_major> b0, b1;
            wmma::load_matrix_sync(a0, &As[(wm * 32) * GLD + kk], GLD);
            wmma::load_matrix_sync(a1, &As[(wm * 32 + 16) * GLD + kk], GLD);
            wmma::load_matrix_sync(b0, &Bs[(wn * 32) * GLD + kk], GLD);
            wmma::load_matrix_sync(b1, &Bs[(wn * 32 + 16) * GLD + kk], GLD);
            wmma::mma_sync(acc[0][0], a0, b0, acc[0][0]);
            wmma::mma_sync(acc[0][1], a0, b1, acc[0][1]);
            wmma::mma_sync(acc[1][0], a1, b0, acc[1][0]);
            wmma::mma_sync(acc[1][1], a1, b1, acc[1][1]);
        }

        if (it + 2 < NIT) {
            const __nv_bfloat16 *A, *B;
            int kt;
            getAB(it + 2, A, B, kt);
            gemm_stage_load(stA((it + 2) % GSTAGE), stB((it + 2) % GSTAGE), A, B,
                            m0, n0, kt, tid);
        }
    }

    if (Ch == nullptr) {
#pragma unroll
        for (int i = 0; i < 2; i++)
#pragma unroll
            for (int j = 0; j < 2; j++)
                wmma::store_matrix_sync(
                    &C[(size_t)(m0 + wm * 32 + i * 16) * Cld + cn0 + wn * 32 +
                       j * 16],
                    acc[i][j], Cld, wmma::mem_row_major);
    } else {
        // split-bf16 epilogue: stage through smem (stage buffers now dead)
        __syncthreads();
        float* Of = (float*)sh;  // 128x64 fp32 = 32KB < GEMM_SMEM
#pragma unroll
        for (int i = 0; i < 2; i++)
#pragma unroll
            for (int j = 0; j < 2; j++)
                wmma::store_matrix_sync(
                    &Of[(wm * 32 + i * 16) * GBN + wn * 32 + j * 16], acc[i][j],
                    GBN, wmma::mem_row_major);
        __syncthreads();
#pragma unroll
        for (int e = 0; e < GBM * GBN / 256; e++) {
            int idx = tid + e * 256;
            int r = idx >> 6, c = idx & 63;
            split_store(Ch, Cl, (m0 + r) * D + n0 + c, Of[r * GBN + c]);
        }
    }
}

// merged Q/K/V/U/gate projection: 49 n-blocks (48 qkvu + 1 gate)
// V blocks (z==2) emit split-bf16 directly.
__global__ void __launch_bounds__(256) gemm_qkvu_tc(float* __restrict__ gq_unused) {
    int bx = blockIdx.x;
    int m0 = blockIdx.y * GBM;
    if (bx < 48) {
        int nglob = bx * GBN;
        int z = nglob / D;
        int n0 = nglob % D;
        if (z == 2) {
            gemm_body(g_Xh, g_Xl, g_Wh + (size_t)2 * D * D,
                      g_Wl + (size_t)2 * D * D, nullptr, m0, n0, D, n0, g_vh,
                      g_vl);
        } else {
            float* Cs[4] = {g_q, g_k, nullptr, g_u};
            gemm_body(g_Xh, g_Xl, g_Wh + (size_t)z * D * D,
                      g_Wl + (size_t)z * D * D, Cs[z], m0, n0, D, n0, nullptr,
                      nullptr);
        }
    } else {
        gemm_body(g_Xh, g_Xl, g_Wgph, g_Wgpl, g_gatep, m0, 0, 64, 0, nullptr,
                  nullptr);
    }
}

__global__ void __launch_bounds__(256) gemm_out_tc(float* __restrict__ out) {
    int n0 = blockIdx.x * GBN;
    gemm_body(g_lnh, g_lnl, g_Wh + (size_t)4 * D * D, g_Wl + (size_t)4 * D * D,
              out, blockIdx.y * GBM, n0, D, n0, nullptr, nullptr);
}

// ---------------- fused: RoPE+normalize (split-emit)  ||  chunked cumsum ----
#define ROPE_BLOCKS 1536   // LH warps / 8 warps per block (warp per (l,h))
#define CUMSUM_BLOCKS 384  // (D/8) channel-groups x 4 chunks

__global__ void __launch_bounds__(256) rope_cumsum_fused() {
    __shared__ float sm[32][9];
    const int bx = blockIdx.x;
    const int tid = threadIdx.x;

    if (bx < ROPE_BLOCKS) {
        // ---- RoPE + L2 norm path (q, k only; v handled in GEMM epilogue) ----
        int gw = bx * 8 + (tid >> 5);
        int lane = tid & 31;
        int l = gw / NH, h = gw % NH;
        int base = l * D + h * HD;
        int i0 = lane >> 1;
        const float LN1E4_32 = 0.28782313662425572f;
        float f0 = expf(-(float)i0 * LN1E4_32);
        float f1 = expf(-(float)(i0 + 16) * LN1E4_32);
        float a0 = (float)l * f0;
        float a1 = (float)l * f1;
        float c0 = cosf(a0), sn0 = sinf(a0);
        float c1 = cosf(a1), sn1 = sinf(a1);

        {
            float x0 = g_q[base + lane], x1 = g_q[base + lane + 32];
            float r0 = x0 * c0 - x1 * sn0;
            float r1 = x1 * c1 + x0 * sn1;
            float nn = r0 * r0 + r1 * r1;
#pragma unroll
            for (int o = 16; o; o >>= 1) nn += __shfl_xor_sync(0xffffffffu, nn, o);
            float inv = 1.f / fmaxf(sqrtf(nn), 1e-12f);
            split_store(g_qh, g_ql, base + lane, r0 * inv);
            split_store(g_qh, g_ql, base + lane + 32, r1 * inv);
        }
        {
            float x0 = g_k[base + lane], x1 = g_k[base + lane + 32];
            float r0 = x0 * c0 - x1 * sn0;
            float r1 = x1 * c1 + x0 * sn1;
            float nn = r0 * r0 + r1 * r1;
#pragma unroll
            for (int o = 16; o; o >>= 1) nn += __shfl_xor_sync(0xffffffffu, nn, o);
            float inv = 1.f / fmaxf(sqrtf(nn), 1e-12f);
            split_store(g_kh, g_kl, base + lane, r0 * inv);
            split_store(g_kh, g_kl, base + lane + 32, r1 * inv);
        }
    } else {
        // ---- chunked cumsum path ----
        int bc = bx - ROPE_BLOCKS;
        const int c0 = (bc % 96) * 8;
        const int base = (bc / 96) * 256;
        const int w = tid >> 5, lane = tid & 31;
        const int lr = tid >> 3, lc = tid & 7;
        float carry = 0.f;
#pragma unroll 1
        for (int l0 = base; l0 < base + 256; l0 += 32) {
            float vin = g_u[(l0 + lr) * D + c0 + lc];
            __syncthreads();
            sm[lr][lc] = vin;
            __syncthreads();
            float v = sm[lane][w];
#pragma unroll
            for (int o = 1; o < 32; o <<= 1) {
                float n = __shfl_up_sync(0xffffffffu, v, o);
                if (lane >= o) v += n;
            }
            v += carry;
            carry = __shfl_sync(0xffffffffu, v, 31);
            sm[lane][w] = v;
            __syncthreads();
            g_usum[(l0 + lr) * D + c0 + lc] = sm[lr][lc];
        }
        if (lane == 0) g_ct[(bc / 96) * D + c0 + w] = carry;
    }
}

// ---------------- s_i = -(1/sqrt(d)) * u . bar_u (inline chunk prefix) ------
__global__ void compute_s(const float* __restrict__ pmu,
                          const float* __restrict__ plt) {
    int gw = (blockIdx.x * blockDim.x + threadIdx.x) >> 5;
    int lane = threadIdx.x & 31;
    if (gw >= LH) return;
    int l = gw / NH, h = gw % NH;
    float lt = expf(fminf(fmaxf(plt[h], -50.f), 30.f));
    float t = (float)(l + 1);
    float inv_den = 1.f / (lt + t);
    int chunk = l >> 8;
    float acc = 0.f;
#pragma unroll
    for (int r = 0; r < 2; r++) {
        int i = lane + r * 32;
        int ch = h * HD + i;
        float off = 0.f;
        for (int c = 0; c < chunk; c++) off += g_ct[c * D + ch];
        float uu = g_u[l * D + ch];
        float us = g_usum[l * D + ch] + off;
        float bu = (lt * pmu[ch] + us) * inv_den;
        acc = fmaf(uu, bu, acc);
    }
#pragma unroll
    for (int o = 16; o; o >>= 1) acc += __shfl_xor_sync(0xffffffffu, acc, o);
    if (lane == 0) g_s[l * NH + h] = -acc * 0.125f;
}

// ---------------- per-head: max, scans, gate coefficients -------------------
__global__ void __launch_bounds__(1024) head_scan() {
    __shared__ float she[1024];
    __shared__ float shp[1024];
    const int h = blockIdx.x;
    const int l = threadIdx.x;
    float s = g_s[l * NH + h];
    she[l] = s;
    __syncthreads();
    for (int off = 512; off > 0; off >>= 1) {
        if (l < off) she[l] = fmaxf(she[l], she[l + off]);
        __syncthreads();
    }
    float smax = she[0];
    __syncthreads();
    float e = expf(s - smax);
    float ev = e, pv = s;
    she[l] = ev;
    shp[l] = pv;
    __syncthreads();
    for (int off = 1; off < 1024; off <<= 1) {
        float ae = 0.f, ap = 0.f;
        if (l >= off) { ae = she[l - off]; ap = shp[l - off]; }
        __syncthreads();
        ev += ae;
        pv += ap;
        she[l] = ev;
        shp[l] = pv;
        __syncthreads();
    }
    float g1 = g_gatep[l * 64 + h * 3 + 0];
    float gh = g_gatep[l * 64 + h * 3 + 1];
    float s1 = 1.f / (1.f + expf(-g1));
    float shg = 1.f / (1.f + expf(-gh));
    float t = (float)(l + 1);
    float a = shg / (ev + 1e-12f);
    float b = (s1 - shg) / t;
    float gm = -(b * pv + shg) / t;
    int o = l * NH + h;
    g_es[o] = e;
    g_al[o] = a;
    g_be[o] = b;
    g_ga[o] = gm;
}

// ---------------- tensor-core weighted causal attention + LayerNorm ---------
#define ALD 72
#define SLD 68
#define ATTN_SMEM (8 * 64 * ALD * 2 + 64 * SLD * 4)

__global__ void __launch_bounds__(256) attn_tc() {
    extern __shared__ __nv_bfloat16 ash[];
    __nv_bfloat16* Qh = ash;
    __nv_bfloat16* Ql = ash + 1 * 64 * ALD;
    __nv_bfloat16* Kh = ash + 2 * 64 * ALD;
    __nv_bfloat16* Kl = ash + 3 * 64 * ALD;
    __nv_bfloat16* Vh = ash + 4 * 64 * ALD;
    __nv_bfloat16* Vl = ash + 5 * 64 * ALD;
    __nv_bfloat16* Sh = ash + 6 * 64 * ALD;
    __nv_bfloat16* Sl = ash + 7 * 64 * ALD;
    float* Sf = (float*)(ash + 8 * 64 * ALD);
    __shared__ float cA[64], cB[64], cG[64], sES[64], sS[64];

    const int h = blockIdx.y;
    const int lt = 15 - blockIdx.x;
    const int l0 = lt * 64;
    const int tid = threadIdx.x;
    const int warp = tid >> 5;
    const int wm = warp >> 1, wn = warp & 1;

#pragma unroll
    for (int it = 0; it < 2; it++) {
        int idx = tid + it * 256;
        int r = idx >> 3, c = (idx & 7) * 8;
        *(uint4*)&Qh[r * ALD + c] = *(const uint4*)&g_qh[(l0 + r) * D + h * HD + c];
        *(uint4*)&Ql[r * ALD + c] = *(const uint4*)&g_ql[(l0 + r) * D + h * HD + c];
    }
    if (tid < 64) {
        cA[tid] = g_al[(l0 + tid) * NH + h];
        cB[tid] = g_be[(l0 + tid) * NH + h];
        cG[tid] = g_ga[(l0 + tid) * NH + h];
    }

    wmma::fragment<wmma::accumulator, 16, 16, 16, float> acc_o[2];
    wmma::fill_fragment(acc_o[0], 0.f);
    wmma::fill_fragment(acc_o[1], 0.f);

    const int r_ = tid >> 2;
    const int cb_ = (tid & 3) * 16;

#pragma unroll 1
    for (int jt = 0; jt <= lt; jt++) {
        const int j0 = jt * 64;
        __syncthreads();
#pragma unroll
        for (int it = 0; it < 2; it++) {
            int idx = tid + it * 256;
            int r = idx >> 3, c = (idx & 7) * 8;
            *(uint4*)&Kh[r * ALD + c] = *(const uint4*)&g_kh[(j0 + r) * D + h * HD + c];
            *(uint4*)&Kl[r * ALD + c] = *(const uint4*)&g_kl[(j0 + r) * D + h * HD + c];
            *(uint4*)&Vh[r * ALD + c] = *(const uint4*)&g_vh[(j0 + r) * D + h * HD + c];
            *(uint4*)&Vl[r * ALD + c] = *(const uint4*)&g_vl[(j0 + r) * D + h * HD + c];
        }
        if (tid < 64) {
            sES[tid] = g_es[(j0 + tid) * NH + h];
            sS[tid] = g_s[(j0 + tid) * NH + h];
        }
        __syncthreads();

        wmma::fragment<wmma::accumulator, 16, 16, 16, float> acc_s[2];
        wmma::fill_fragment(acc_s[0], 0.f);
        wmma::fill_fragment(acc_s[1], 0.f);
#pragma unroll
        for (int p = 0; p < 3; p++) {
            const __nv_bfloat16* Aq = (p == 1) ? Ql : Qh;
            const __nv_bfloat16* Bk = (p == 2) ? Kl : Kh;
#pragma unroll
            for (int kk = 0; kk < 64; kk += 16) {
                wmma::fragment<wmma::matrix_a, 16, 16, 16, __nv_bfloat16,
                               wmma::row_major> af;
                wmma::load_matrix_sync(af, &Aq[(wm * 16) * ALD + kk], ALD);
#pragma unroll
                for (int jn = 0; jn < 2; jn++) {
                    wmma::fragment<wmma::matrix_b, 16, 16, 16, __nv_bfloat16,
                                   wmma::col_major> bf;
                    wmma::load_matrix_sync(
                        bf, &Bk[(wn * 32 + jn * 16) * ALD + kk], ALD);
                    wmma::mma_sync(acc_s[jn], af, bf, acc_s[jn]);
                }
            }
        }
#pragma unroll
        for (int jn = 0; jn < 2; jn++)
            wmma::store_matrix_sync(&Sf[(wm * 16) * SLD + wn * 32 + jn * 16],
                                    acc_s[jn], SLD, wmma::mem_row_major);
        __syncthreads();

        {
            float Ar = cA[r_], Br = cB[r_], Gr = cG[r_];
            int gl = l0 + r_;
#pragma unroll
            for (int i = 0; i < 16; i++) {
                int c = cb_ + i;
                float w = Ar * sES[c] + Br * sS[c] + Gr;
                float sv = (j0 + c <= gl) ? Sf[r_ * SLD + c] * w : 0.f;
                __nv_bfloat16 hb = __float2bfloat16(sv);
                Sh[r_ * ALD + c] = hb;
                Sl[r_ * ALD + c] = __float2bfloat16(sv - __bfloat162float(hb));
            }
        }
        __syncthreads();

#pragma unroll
        for (int p = 0; p < 3; p++) {
            const __nv_bfloat16* Asm = (p == 1) ? Sl : Sh;
            const __nv_bfloat16* Bvm = (p == 2) ? Vl : Vh;
#pragma unroll
            for (int kk = 0; kk < 64; kk += 16) {
                wmma::fragment<wmma::matrix_a, 16, 16, 16, __nv_bfloat16,
                               wmma::row_major> af;
                wmma::load_matrix_sync(af, &Asm[(wm * 16) * ALD + kk], ALD);
#pragma unroll
                for (int jn = 0; jn < 2; jn++) {
                    wmma::fragment<wmma::matrix_b, 16, 16, 16, __nv_bfloat16,
                                   wmma::row_major> bf;
                    wmma::load_matrix_sync(bf, &Bvm[kk * ALD + wn * 32 + jn * 16],
                                           ALD);
                    wmma::mma_sync(acc_o[jn], af, bf, acc_o[jn]);
                }
            }
        }
    }

    __syncthreads();
#pragma unroll
    for (int jn = 0; jn < 2; jn++)
        wmma::store_matrix_sync(&Sf[(wm * 16) * SLD + wn * 32 + jn * 16],
                                acc_o[jn], SLD, wmma::mem_row_major);
    __syncthreads();
    {
        float vals[16];
        float sum = 0.f;
#pragma unroll
        for (int i = 0; i < 16; i++) {
            vals[i] = Sf[r_ * SLD + cb_ + i];
            sum += vals[i];
        }
        sum += __shfl_xor_sync(0xffffffffu, sum, 1);
        sum += __shfl_xor_sync(0xffffffffu, sum, 2);
        float mean = sum * (1.f / 64.f);
        float vs = 0.f;
#pragma unroll
        for (int i = 0; i < 16; i++) {
            vals[i] -= mean;
            vs += vals[i] * vals[i];
        }
        vs += __shfl_xor_sync(0xffffffffu, vs, 1);
        vs += __shfl_xor_sync(0xffffffffu, vs, 2);
        float inv = rsqrtf(vs * (1.f / 64.f) + 1e-5f);
        int off = (l0 + r_) * D + h * HD + cb_;
#pragma unroll
        for (int i = 0; i < 16; i += 2) {
            float v0 = vals[i] * inv, v1 = vals[i + 1] * inv;
            __nv_bfloat16 h0 = __float2bfloat16(v0);
            __nv_bfloat16 h1 = __float2bfloat16(v1);
            *(__nv_bfloat162*)&g_lnh[off + i] = __nv_bfloat162(h0, h1);
            *(__nv_bfloat162*)&g_lnl[off + i] = __nv_bfloat162(
                __float2bfloat16(v0 - __bfloat162float(h0)),
                __float2bfloat16(v1 - __bfloat162float(h1)));
        }
    }
}

// ---------------- launch ----------------------------------------------------
extern "C" void kernel_launch(void* const* d_in, const int* in_sizes, int n_in,
                              void* d_out, int out_size) {
    const float* X = (const float*)d_in[0];
    const float* Wq = (const float*)d_in[1];
    const float* Wk = (const float*)d_in[2];
    const float* Wv = (const float*)d_in[3];
    const float* Wu = (const float*)d_in[4];
    const float* Wg = (const float*)d_in[5];
    const float* Wo = (const float*)d_in[6];
    const float* pmu = (const float*)d_in[7];
    const float* plt = (const float*)d_in[8];
    float* out = (float*)d_out;

    cudaFuncSetAttribute(attn_tc, cudaFuncAttributeMaxDynamicSharedMemorySize,
                         ATTN_SMEM);
    cudaFuncSetAttribute(gemm_qkvu_tc, cudaFuncAttributeMaxDynamicSharedMemorySize,
                         GEMM_SMEM);
    cudaFuncSetAttribute(gemm_out_tc, cudaFuncAttributeMaxDynamicSharedMemorySize,
                         GEMM_SMEM);

    convert_inputs<<<dim3(96, 7), 256>>>(X, Wq, Wk, Wv, Wu, Wo, Wg);

    // merged Q/K/V/U + gate projection (V emits split-bf16 in epilogue)
    gemm_qkvu_tc<<<dim3(49, L / GBM), 256, GEMM_SMEM>>>(nullptr);

    // fused RoPE/normalize (q,k) + chunked cumsum
    rope_cumsum_fused<<<ROPE_BLOCKS + CUMSUM_BLOCKS, 256>>>();

    compute_s<<<(LH * 32 + 255) / 256, 256>>>(pmu, plt);
    head_scan<<<NH, 1024>>>();

    attn_tc<<<dim3(16, NH), 256, ATTN_SMEM>>>();

    gemm_out_tc<<<dim3(D / GBN, L / GBM), 256, GEMM_SMEM>>>(out);
}

// round 14
// speedup vs baseline: 2.1491x; 1.3462x over previous
#include <cuda_runtime.h>
#include <cuda_fp16.h>
#include <mma.h>
#include <math.h>
#include <cstdint>

using namespace nvcuda;

#define L 1024
#define D 768
#define NH 12
#define HD 64
#define LH (L*NH)

// ---------------- scratch (device globals; no allocation allowed) ----------
__device__ float g_q[L*D];
__device__ float g_k[L*D];
__device__ float g_v[L*D];
__device__ float g_u[L*D];
__device__ float g_usum[L*D];
__device__ float g_ct[4*D];      // per-chunk totals
__device__ float g_gatep[L*64];  // padded gate output (64-wide)
__device__ float g_s[LH];
__device__ float g_es[LH];
__device__ float g_al[LH];
__device__ float g_be[LH];
__device__ float g_ga[LH];

// split-fp16 buffers (weights: hi only — residual unused in 2-pass GEMM)
__device__ __half g_Xh[L*D];
__device__ __half g_Xl[L*D];
__device__ __half g_Wh[5*D*D];   // Wq,Wk,Wv,Wu,Wo (hi)
__device__ __half g_Wgph[64*D];  // Wg padded to 64 rows (zero-init, hi)
__device__ __half g_lnh[L*D];
__device__ __half g_lnl[L*D];
__device__ __half g_qh[L*D];
__device__ __half g_ql[L*D];
__device__ __half g_kh[L*D];
__device__ __half g_kl[L*D];
__device__ __half g_vh[L*D];
__device__ __half g_vl[L*D];

// ---------------- fp32 -> fp16 conversion (X: hi+lo, W: hi only) ------------
__global__ void convert_inputs(const float* __restrict__ X,
                               const float* __restrict__ Wq,
                               const float* __restrict__ Wk,
                               const float* __restrict__ Wv,
                               const float* __restrict__ Wu,
                               const float* __restrict__ Wo,
                               const float* __restrict__ Wg) {
    int z = blockIdx.y;
    if (z == 0) {
        for (int i = blockIdx.x * blockDim.x + threadIdx.x; i < L * D;
             i += gridDim.x * blockDim.x) {
            float v = X[i];
            __half h = __float2half_rn(v);
            g_Xh[i] = h;
            g_Xl[i] = __float2half_rn(v - __half2float(h));
        }
    } else if (z <= 5) {
        const float* ws[5] = {Wq, Wk, Wv, Wu, Wo};
        const float* src = ws[z - 1];
        __half* dh = g_Wh + (size_t)(z - 1) * D * D;
        for (int i = blockIdx.x * blockDim.x + threadIdx.x; i < D * D;
             i += gridDim.x * blockDim.x)
            dh[i] = __float2half_rn(src[i]);
    } else {
        for (int i = blockIdx.x * blockDim.x + threadIdx.x; i < 36 * D;
             i += gridDim.x * blockDim.x)
            g_Wgph[i] = __float2half_rn(Wg[i]);  // rows 36..63 stay 0
    }
}

// ---------------- helpers -----------------------------------------------------
__device__ __forceinline__ void cp16(void* dst, const void* src) {
    unsigned d = (unsigned)__cvta_generic_to_shared(dst);
    asm volatile("cp.async.cg.shared.global [%0], [%1], 16;" :: "r"(d), "l"(src));
}

__device__ __forceinline__ void split_store(__half* dh, __half* dl, int idx,
                                            float v) {
    __half hb = __float2half_rn(v);
    dh[idx] = hb;
    dl[idx] = __float2half_rn(v - __half2float(hb));
}

// ---------------- split-fp16 tensor-core GEMM (2-pass, 3-stage cp.async) ----
// C = A·B^T  via  Ah·Bh + Al·Bh   (drops Ah·Bl ~ 2^-11 rel; B = weights)
#define GBM 128
#define GBN 64
#define GBK 64
#define GLD 72
#define GSTAGE 3
#define GEMM_SMEM ((GBM + GBN) * GLD * 2 * GSTAGE)   // 82944 bytes

__device__ __forceinline__ void gemm_stage_load(
    __half* As, __half* Bs,
    const __half* __restrict__ A, const __half* __restrict__ B,
    int m0, int n0, int kt, int tid) {
#pragma unroll
    for (int i = 0; i < 4; i++) {
        int idx = tid + i * 256;
        int r = idx >> 3, c8 = (idx & 7) * 8;
        cp16(&As[r * GLD + c8], &A[(size_t)(m0 + r) * D + kt + c8]);
    }
#pragma unroll
    for (int i = 0; i < 2; i++) {
        int idx = tid + i * 256;
        int r = idx >> 3, c8 = (idx & 7) * 8;
        cp16(&Bs[r * GLD + c8], &B[(size_t)(n0 + r) * D + kt + c8]);
    }
    asm volatile("cp.async.commit_group;");
}

__device__ __forceinline__ void gemm_body(
    const __half* __restrict__ Ah, const __half* __restrict__ Al,
    const __half* __restrict__ Bh,
    float* __restrict__ C, int m0, int n0, int Cld, int cn0) {
    extern __shared__ __half sh[];
    const int tid = threadIdx.x;
    const int warp = tid >> 5;
    const int wm = warp >> 1, wn = warp & 1;

    wmma::fragment<wmma::accumulator, 16, 16, 16, float> acc[2][2];
#pragma unroll
    for (int i = 0; i < 2; i++)
#pragma unroll
        for (int j = 0; j < 2; j++) wmma::fill_fragment(acc[i][j], 0.f);

    const int NIT = 24;  // 2 segments x 12 k-tiles
    auto stA = [&](int s) { return sh + (size_t)s * (GBM + GBN) * GLD; };
    auto stB = [&](int s) { return sh + (size_t)s * (GBM + GBN) * GLD + GBM * GLD; };
    auto getAB = [&](int it, const __half*& A, const __half*& B, int& kt) {
        int seg = it / 12;
        kt = (it % 12) * GBK;
        A = seg ? Al : Ah;
        B = Bh;
    };

    {
        const __half *A, *B;
        int kt;
        getAB(0, A, B, kt);
        gemm_stage_load(stA(0), stB(0), A, B, m0, n0, kt, tid);
        getAB(1, A, B, kt);
        gemm_stage_load(stA(1), stB(1), A, B, m0, n0, kt, tid);
    }

#pragma unroll 1
    for (int it = 0; it < NIT; it++) {
        if (it < NIT - 1) asm volatile("cp.async.wait_group 1;");
        else              asm volatile("cp.async.wait_group 0;");
        __syncthreads();

        const __half* As = stA(it % GSTAGE);
        const __half* Bs = stB(it % GSTAGE);
#pragma unroll
        for (int kk = 0; kk < GBK; kk += 16) {
            wmma::fragment<wmma::matrix_a, 16, 16, 16, __half,
                           wmma::row_major> a0, a1;
            wmma::fragment<wmma::matrix_b, 16, 16, 16, __half,
                           wmma::col_major> b0, b1;
            wmma::load_matrix_sync(a0, &As[(wm * 32) * GLD + kk], GLD);
            wmma::load_matrix_sync(a1, &As[(wm * 32 + 16) * GLD + kk], GLD);
            wmma::load_matrix_sync(b0, &Bs[(wn * 32) * GLD + kk], GLD);
            wmma::load_matrix_sync(b1, &Bs[(wn * 32 + 16) * GLD + kk], GLD);
            wmma::mma_sync(acc[0][0], a0, b0, acc[0][0]);
            wmma::mma_sync(acc[0][1], a0, b1, acc[0][1]);
            wmma::mma_sync(acc[1][0], a1, b0, acc[1][0]);
            wmma::mma_sync(acc[1][1], a1, b1, acc[1][1]);
        }

        if (it + 2 < NIT) {
            const __half *A, *B;
            int kt;
            getAB(it + 2, A, B, kt);
            gemm_stage_load(stA((it + 2) % GSTAGE), stB((it + 2) % GSTAGE), A, B,
                            m0, n0, kt, tid);
        }
    }

#pragma unroll
    for (int i = 0; i < 2; i++)
#pragma unroll
        for (int j = 0; j < 2; j++)
            wmma::store_matrix_sync(
                &C[(size_t)(m0 + wm * 32 + i * 16) * Cld + cn0 + wn * 32 + j * 16],
                acc[i][j], Cld, wmma::mem_row_major);
}

// merged Q/K/V/U/gate projection: 49 n-blocks (48 qkvu + 1 gate)
__global__ void __launch_bounds__(256) gemm_qkvu_tc() {
    int bx = blockIdx.x;
    int m0 = blockIdx.y * GBM;
    if (bx < 48) {
        int nglob = bx * GBN;
        int z = nglob / D;
        int n0 = nglob % D;
        float* Cs[4] = {g_q, g_k, g_v, g_u};
        gemm_body(g_Xh, g_Xl, g_Wh + (size_t)z * D * D, Cs[z], m0, n0, D, n0);
    } else {
        gemm_body(g_Xh, g_Xl, g_Wgph, g_gatep, m0, 0, 64, 0);
    }
}

__global__ void __launch_bounds__(256) gemm_out_tc(float* __restrict__ out) {
    int n0 = blockIdx.x * GBN;
    gemm_body(g_lnh, g_lnl, g_Wh + (size_t)4 * D * D, out, blockIdx.y * GBM, n0,
              D, n0);
}

// ---------------- fused: RoPE+normalize (split-emit)  ||  chunked cumsum ----
#define ROPE_BLOCKS 1536   // LH warps / 8 warps per block (warp per (l,h))
#define CUMSUM_BLOCKS 384  // (D/8) channel-groups x 4 chunks

__global__ void __launch_bounds__(256) rope_cumsum_fused() {
    __shared__ float sm[32][9];
    const int bx = blockIdx.x;
    const int tid = threadIdx.x;

    if (bx < ROPE_BLOCKS) {
        int gw = bx * 8 + (tid >> 5);
        int lane = tid & 31;
        int l = gw / NH, h = gw % NH;
        int base = l * D + h * HD;
        int i0 = lane >> 1;
        const float LN1E4_32 = 0.28782313662425572f;
        float f0 = expf(-(float)i0 * LN1E4_32);
        float f1 = expf(-(float)(i0 + 16) * LN1E4_32);
        float a0 = (float)l * f0;
        float a1 = (float)l * f1;
        float c0 = cosf(a0), sn0 = sinf(a0);
        float c1 = cosf(a1), sn1 = sinf(a1);

        {
            float x0 = g_q[base + lane], x1 = g_q[base + lane + 32];
            float r0 = x0 * c0 - x1 * sn0;
            float r1 = x1 * c1 + x0 * sn1;
            float nn = r0 * r0 + r1 * r1;
#pragma unroll
            for (int o = 16; o; o >>= 1) nn += __shfl_xor_sync(0xffffffffu, nn, o);
            float inv = 1.f / fmaxf(sqrtf(nn), 1e-12f);
            split_store(g_qh, g_ql, base + lane, r0 * inv);
            split_store(g_qh, g_ql, base + lane + 32, r1 * inv);
        }
        {
            float x0 = g_k[base + lane], x1 = g_k[base + lane + 32];
            float r0 = x0 * c0 - x1 * sn0;
            float r1 = x1 * c1 + x0 * sn1;
            float nn = r0 * r0 + r1 * r1;
#pragma unroll
            for (int o = 16; o; o >>= 1) nn += __shfl_xor_sync(0xffffffffu, nn, o);
            float inv = 1.f / fmaxf(sqrtf(nn), 1e-12f);
            split_store(g_kh, g_kl, base + lane, r0 * inv);
            split_store(g_kh, g_kl, base + lane + 32, r1 * inv);
        }
        {
            split_store(g_vh, g_vl, base + lane, g_v[base + lane]);
            split_store(g_vh, g_vl, base + lane + 32, g_v[base + lane + 32]);
        }
    } else {
        int bc = bx - ROPE_BLOCKS;
        const int c0 = (bc % 96) * 8;
        const int base = (bc / 96) * 256;
        const int w = tid >> 5, lane = tid & 31;
        const int lr = tid >> 3, lc = tid & 7;
        float carry = 0.f;
#pragma unroll 1
        for (int l0 = base; l0 < base + 256; l0 += 32) {
            float vin = g_u[(l0 + lr) * D + c0 + lc];
            __syncthreads();
            sm[lr][lc] = vin;
            __syncthreads();
            float v = sm[lane][w];
#pragma unroll
            for (int o = 1; o < 32; o <<= 1) {
                float n = __shfl_up_sync(0xffffffffu, v, o);
                if (lane >= o) v += n;
            }
            v += carry;
            carry = __shfl_sync(0xffffffffu, v, 31);
            sm[lane][w] = v;
            __syncthreads();
            g_usum[(l0 + lr) * D + c0 + lc] = sm[lr][lc];
        }
        if (lane == 0) g_ct[(bc / 96) * D + c0 + w] = carry;
    }
}

// ---------------- s_i = -(1/sqrt(d)) * u . bar_u (inline chunk prefix) ------
__global__ void compute_s(const float* __restrict__ pmu,
                          const float* __restrict__ plt) {
    int gw = (blockIdx.x * blockDim.x + threadIdx.x) >> 5;
    int lane = threadIdx.x & 31;
    if (gw >= LH) return;
    int l = gw / NH, h = gw % NH;
    float lt = expf(fminf(fmaxf(plt[h], -50.f), 30.f));
    float t = (float)(l + 1);
    float inv_den = 1.f / (lt + t);
    int chunk = l >> 8;
    float acc = 0.f;
#pragma unroll
    for (int r = 0; r < 2; r++) {
        int i = lane + r * 32;
        int ch = h * HD + i;
        float off = 0.f;
        for (int c = 0; c < chunk; c++) off += g_ct[c * D + ch];
        float uu = g_u[l * D + ch];
        float us = g_usum[l * D + ch] + off;
        float bu = (lt * pmu[ch] + us) * inv_den;
        acc = fmaf(uu, bu, acc);
    }
#pragma unroll
    for (int o = 16; o; o >>= 1) acc += __shfl_xor_sync(0xffffffffu, acc, o);
    if (lane == 0) g_s[l * NH + h] = -acc * 0.125f;
}

// ---------------- per-head: max, scans, gate coefficients -------------------
__global__ void __launch_bounds__(1024) head_scan() {
    __shared__ float she[1024];
    __shared__ float shp[1024];
    const int h = blockIdx.x;
    const int l = threadIdx.x;
    float s = g_s[l * NH + h];
    she[l] = s;
    __syncthreads();
    for (int off = 512; off > 0; off >>= 1) {
        if (l < off) she[l] = fmaxf(she[l], she[l + off]);
        __syncthreads();
    }
    float smax = she[0];
    __syncthreads();
    float e = expf(s - smax);
    float ev = e, pv = s;
    she[l] = ev;
    shp[l] = pv;
    __syncthreads();
    for (int off = 1; off < 1024; off <<= 1) {
        float ae = 0.f, ap = 0.f;
        if (l >= off) { ae = she[l - off]; ap = shp[l - off]; }
        __syncthreads();
        ev += ae;
        pv += ap;
        she[l] = ev;
        shp[l] = pv;
        __syncthreads();
    }
    float g1 = g_gatep[l * 64 + h * 3 + 0];
    float gh = g_gatep[l * 64 + h * 3 + 1];
    float s1 = 1.f / (1.f + expf(-g1));
    float shg = 1.f / (1.f + expf(-gh));
    float t = (float)(l + 1);
    float a = shg / (ev + 1e-12f);
    float b = (s1 - shg) / t;
    float gm = -(b * pv + shg) / t;
    int o = l * NH + h;
    g_es[o] = e;
    g_al[o] = a;
    g_be[o] = b;
    g_ga[o] = gm;
}

// ---------------- tensor-core weighted causal attention + LayerNorm ---------
#define ALD 72
#define SLD 68
#define ATTN_SMEM (8 * 64 * ALD * 2 + 64 * SLD * 4)

__global__ void __launch_bounds__(256) attn_tc() {
    extern __shared__ __half ash[];
    __half* Qh = ash;
    __half* Ql = ash + 1 * 64 * ALD;
    __half* Kh = ash + 2 * 64 * ALD;
    __half* Kl = ash + 3 * 64 * ALD;
    __half* Vh = ash + 4 * 64 * ALD;
    __half* Vl = ash + 5 * 64 * ALD;
    __half* Sh = ash + 6 * 64 * ALD;
    __half* Sl = ash + 7 * 64 * ALD;
    float* Sf = (float*)(ash + 8 * 64 * ALD);
    __shared__ float cA[64], cB[64], cG[64], sES[64], sS[64];

    const int h = blockIdx.y;
    const int lt = 15 - blockIdx.x;
    const int l0 = lt * 64;
    const int tid = threadIdx.x;
    const int warp = tid >> 5;
    const int wm = warp >> 1, wn = warp & 1;

#pragma unroll
    for (int it = 0; it < 2; it++) {
        int idx = tid + it * 256;
        int r = idx >> 3, c = (idx & 7) * 8;
        *(uint4*)&Qh[r * ALD + c] = *(const uint4*)&g_qh[(l0 + r) * D + h * HD + c];
        *(uint4*)&Ql[r * ALD + c] = *(const uint4*)&g_ql[(l0 + r) * D + h * HD + c];
    }
    if (tid < 64) {
        cA[tid] = g_al[(l0 + tid) * NH + h];
        cB[tid] = g_be[(l0 + tid) * NH + h];
        cG[tid] = g_ga[(l0 + tid) * NH + h];
    }

    wmma::fragment<wmma::accumulator, 16, 16, 16, float> acc_o[2];
    wmma::fill_fragment(acc_o[0], 0.f);
    wmma::fill_fragment(acc_o[1], 0.f);

    const int r_ = tid >> 2;
    const int cb_ = (tid & 3) * 16;

#pragma unroll 1
    for (int jt = 0; jt <= lt; jt++) {
        const int j0 = jt * 64;
        __syncthreads();
#pragma unroll
        for (int it = 0; it < 2; it++) {
            int idx = tid + it * 256;
            int r = idx >> 3, c = (idx & 7) * 8;
            *(uint4*)&Kh[r * ALD + c] = *(const uint4*)&g_kh[(j0 + r) * D + h * HD + c];
            *(uint4*)&Kl[r * ALD + c] = *(const uint4*)&g_kl[(j0 + r) * D + h * HD + c];
            *(uint4*)&Vh[r * ALD + c] = *(const uint4*)&g_vh[(j0 + r) * D + h * HD + c];
            *(uint4*)&Vl[r * ALD + c] = *(const uint4*)&g_vl[(j0 + r) * D + h * HD + c];
        }
        if (tid < 64) {
            sES[tid] = g_es[(j0 + tid) * NH + h];
            sS[tid] = g_s[(j0 + tid) * NH + h];
        }
        __syncthreads();

        wmma::fragment<wmma::accumulator, 16, 16, 16, float> acc_s[2];
        wmma::fill_fragment(acc_s[0], 0.f);
        wmma::fill_fragment(acc_s[1], 0.f);
#pragma unroll
        for (int p = 0; p < 3; p++) {
            const __half* Aq = (p == 1) ? Ql : Qh;
            const __half* Bk = (p == 2) ? Kl : Kh;
#pragma unroll
            for (int kk = 0; kk < 64; kk += 16) {
                wmma::fragment<wmma::matrix_a, 16, 16, 16, __half,
                               wmma::row_major> af;
                wmma::load_matrix_sync(af, &Aq[(wm * 16) * ALD + kk], ALD);
#pragma unroll
                for (int jn = 0; jn < 2; jn++) {
                    wmma::fragment<wmma::matrix_b, 16, 16, 16, __half,
                                   wmma::col_major> bf;
                    wmma::load_matrix_sync(
                        bf, &Bk[(wn * 32 + jn * 16) * ALD + kk], ALD);
                    wmma::mma_sync(acc_s[jn], af, bf, acc_s[jn]);
                }
            }
        }
#pragma unroll
        for (int jn = 0; jn < 2; jn++)
            wmma::store_matrix_sync(&Sf[(wm * 16) * SLD + wn * 32 + jn * 16],
                                    acc_s[jn], SLD, wmma::mem_row_major);
        __syncthreads();

        {
            float Ar = cA[r_], Br = cB[r_], Gr = cG[r_];
            int gl = l0 + r_;
#pragma unroll
            for (int i = 0; i < 16; i++) {
                int c = cb_ + i;
                float w = Ar * sES[c] + Br * sS[c] + Gr;
                float sv = (j0 + c <= gl) ? Sf[r_ * SLD + c] * w : 0.f;
                __half hb = __float2half_rn(sv);
                Sh[r_ * ALD + c] = hb;
                Sl[r_ * ALD + c] = __float2half_rn(sv - __half2float(hb));
            }
        }
        __syncthreads();

#pragma unroll
        for (int p = 0; p < 3; p++) {
            const __half* Asm = (p == 1) ? Sl : Sh;
            const __half* Bvm = (p == 2) ? Vl : Vh;
#pragma unroll
            for (int kk = 0; kk < 64; kk += 16) {
                wmma::fragment<wmma::matrix_a, 16, 16, 16, __half,
                               wmma::row_major> af;
                wmma::load_matrix_sync(af, &Asm[(wm * 16) * ALD + kk], ALD);
#pragma unroll
                for (int jn = 0; jn < 2; jn++) {
                    wmma::fragment<wmma::matrix_b, 16, 16, 16, __half,
                                   wmma::row_major> bf;
                    wmma::load_matrix_sync(bf, &Bvm[kk * ALD + wn * 32 + jn * 16],
                                           ALD);
                    wmma::mma_sync(acc_o[jn], af, bf, acc_o[jn]);
                }
            }
        }
    }

    __syncthreads();
#pragma unroll
    for (int jn = 0; jn < 2; jn++)
        wmma::store_matrix_sync(&Sf[(wm * 16) * SLD + wn * 32 + jn * 16],
                                acc_o[jn], SLD, wmma::mem_row_major);
    __syncthreads();
    {
        float vals[16];
        float sum = 0.f;
#pragma unroll
        for (int i = 0; i < 16; i++) {
            vals[i] = Sf[r_ * SLD + cb_ + i];
            sum += vals[i];
        }
        sum += __shfl_xor_sync(0xffffffffu, sum, 1);
        sum += __shfl_xor_sync(0xffffffffu, sum, 2);
        float mean = sum * (1.f / 64.f);
        float vs = 0.f;
#pragma unroll
        for (int i = 0; i < 16; i++) {
            vals[i] -= mean;
            vs += vals[i] * vals[i];
        }
        vs += __shfl_xor_sync(0xffffffffu, vs, 1);
        vs += __shfl_xor_sync(0xffffffffu, vs, 2);
        float inv = rsqrtf(vs * (1.f / 64.f) + 1e-5f);
        int off = (l0 + r_) * D + h * HD + cb_;
#pragma unroll
        for (int i = 0; i < 16; i += 2) {
            float v0 = vals[i] * inv, v1 = vals[i + 1] * inv;
            __half h0 = __float2half_rn(v0);
            __half h1 = __float2half_rn(v1);
            *(__half2*)&g_lnh[off + i] = __halves2half2(h0, h1);
            *(__half2*)&g_lnl[off + i] = __halves2half2(
                __float2half_rn(v0 - __half2float(h0)),
                __float2half_rn(v1 - __half2float(h1)));
        }
    }
}

// ---------------- launch ----------------------------------------------------
extern "C" void kernel_launch(void* const* d_in, const int* in_sizes, int n_in,
                              void* d_out, int out_size) {
    const float* X = (const float*)d_in[0];
    const float* Wq = (const float*)d_in[1];
    const float* Wk = (const float*)d_in[2];
    const float* Wv = (const float*)d_in[3];
    const float* Wu = (const float*)d_in[4];
    const float* Wg = (const float*)d_in[5];
    const float* Wo = (const float*)d_in[6];
    const float* pmu = (const float*)d_in[7];
    const float* plt = (const float*)d_in[8];
    float* out = (float*)d_out;

    cudaFuncSetAttribute(attn_tc, cudaFuncAttributeMaxDynamicSharedMemorySize,
                         ATTN_SMEM);
    cudaFuncSetAttribute(gemm_qkvu_tc, cudaFuncAttributeMaxDynamicSharedMemorySize,
                         GEMM_SMEM);
    cudaFuncSetAttribute(gemm_out_tc, cudaFuncAttributeMaxDynamicSharedMemorySize,
                         GEMM_SMEM);

    convert_inputs<<<dim3(96, 7), 256>>>(X, Wq, Wk, Wv, Wu, Wo, Wg);

    // merged Q/K/V/U + gate projection (2-pass split-fp16, 49 n-blocks)
    gemm_qkvu_tc<<<dim3(49, L / GBM), 256, GEMM_SMEM>>>();

    // fused RoPE/normalize (q,k,v) + chunked cumsum
    rope_cumsum_fused<<<ROPE_BLOCKS + CUMSUM_BLOCKS, 256>>>();

    compute_s<<<(LH * 32 + 255) / 256, 256>>>(pmu, plt);
    head_scan<<<NH, 1024>>>();

    attn_tc<<<dim3(16, NH), 256, ATTN_SMEM>>>();

    gemm_out_tc<<<dim3(D / GBN, L / GBM), 256, GEMM_SMEM>>>(out);
}

// round 15
// speedup vs baseline: 2.1661x; 1.0079x over previous
#include <cuda_runtime.h>
#include <cuda_fp16.h>
#include <mma.h>
#include <math.h>
#include <cstdint>

using namespace nvcuda;

#define L 1024
#define D 768
#define NH 12
#define HD 64
#define LH (L*NH)

// ---------------- scratch (device globals; no allocation allowed) ----------
__device__ float g_q[L*D];
__device__ float g_k[L*D];
__device__ float g_v[L*D];
__device__ float g_u[L*D];
__device__ float g_usum[L*D];
__device__ float g_ct[4*D];      // per-chunk totals
__device__ float g_gatep[L*64];  // padded gate output (64-wide)
__device__ float g_s[LH];
__device__ float g_es[LH];
__device__ float g_al[LH];
__device__ float g_be[LH];
__device__ float g_ga[LH];

// split-fp16 buffers (weights: hi only — residual unused in 2-pass GEMM)
__device__ __half g_Xh[L*D];
__device__ __half g_Xl[L*D];
__device__ __half g_Wh[5*D*D];   // Wq,Wk,Wv,Wu,Wo (hi)
__device__ __half g_Wgph[64*D];  // Wg padded to 64 rows (zero-init, hi)
__device__ __half g_lnh[L*D];
__device__ __half g_lnl[L*D];
__device__ __half g_qh[L*D];
__device__ __half g_ql[L*D];
__device__ __half g_kh[L*D];
__device__ __half g_kl[L*D];
__device__ __half g_vh[L*D];
__device__ __half g_vl[L*D];

// ---------------- fp32 -> fp16 conversion (X: hi+lo, W: hi only) ------------
__global__ void convert_inputs(const float* __restrict__ X,
                               const float* __restrict__ Wq,
                               const float* __restrict__ Wk,
                               const float* __restrict__ Wv,
                               const float* __restrict__ Wu,
                               const float* __restrict__ Wo,
                               const float* __restrict__ Wg) {
    int z = blockIdx.y;
    if (z == 0) {
        for (int i = blockIdx.x * blockDim.x + threadIdx.x; i < L * D;
             i += gridDim.x * blockDim.x) {
            float v = X[i];
            __half h = __float2half_rn(v);
            g_Xh[i] = h;
            g_Xl[i] = __float2half_rn(v - __half2float(h));
        }
    } else if (z <= 5) {
        const float* ws[5] = {Wq, Wk, Wv, Wu, Wo};
        const float* src = ws[z - 1];
        __half* dh = g_Wh + (size_t)(z - 1) * D * D;
        for (int i = blockIdx.x * blockDim.x + threadIdx.x; i < D * D;
             i += gridDim.x * blockDim.x)
            dh[i] = __float2half_rn(src[i]);
    } else {
        for (int i = blockIdx.x * blockDim.x + threadIdx.x; i < 36 * D;
             i += gridDim.x * blockDim.x)
            g_Wgph[i] = __float2half_rn(Wg[i]);  // rows 36..63 stay 0
    }
}

// ---------------- helpers -----------------------------------------------------
__device__ __forceinline__ void cp16(void* dst, const void* src) {
    unsigned d = (unsigned)__cvta_generic_to_shared(dst);
    asm volatile("cp.async.cg.shared.global [%0], [%1], 16;" :: "r"(d), "l"(src));
}

__device__ __forceinline__ void split_store(__half* dh, __half* dl, int idx,
                                            float v) {
    __half hb = __float2half_rn(v);
    dh[idx] = hb;
    dl[idx] = __float2half_rn(v - __half2float(hb));
}

// ---------------- split-fp16 tensor-core GEMM (2-pass, 2-stage cp.async) ----
// C = A·B^T  via  Ah·Bh + Al·Bh   (drops Ah·Bl ~ 2^-11 rel; B = weights)
#define GBM 128
#define GBN 64
#define GBK 64
#define GLD 72
#define GSTAGE 2
#define GEMM_SMEM ((GBM + GBN) * GLD * 2 * GSTAGE)   // 55296 bytes -> 2 blocks/SM

__device__ __forceinline__ void gemm_stage_load(
    __half* As, __half* Bs,
    const __half* __restrict__ A, const __half* __restrict__ B,
    int m0, int n0, int kt, int tid) {
#pragma unroll
    for (int i = 0; i < 4; i++) {
        int idx = tid + i * 256;
        int r = idx >> 3, c8 = (idx & 7) * 8;
        cp16(&As[r * GLD + c8], &A[(size_t)(m0 + r) * D + kt + c8]);
    }
#pragma unroll
    for (int i = 0; i < 2; i++) {
        int idx = tid + i * 256;
        int r = idx >> 3, c8 = (idx & 7) * 8;
        cp16(&Bs[r * GLD + c8], &B[(size_t)(n0 + r) * D + kt + c8]);
    }
    asm volatile("cp.async.commit_group;");
}

__device__ __forceinline__ void gemm_body(
    const __half* __restrict__ Ah, const __half* __restrict__ Al,
    const __half* __restrict__ Bh,
    float* __restrict__ C, int m0, int n0, int Cld, int cn0) {
    extern __shared__ __half sh[];
    const int tid = threadIdx.x;
    const int warp = tid >> 5;
    const int wm = warp >> 1, wn = warp & 1;

    wmma::fragment<wmma::accumulator, 16, 16, 16, float> acc[2][2];
#pragma unroll
    for (int i = 0; i < 2; i++)
#pragma unroll
        for (int j = 0; j < 2; j++) wmma::fill_fragment(acc[i][j], 0.f);

    const int NIT = 24;  // 2 segments x 12 k-tiles
    auto stA = [&](int s) { return sh + (size_t)s * (GBM + GBN) * GLD; };
    auto stB = [&](int s) { return sh + (size_t)s * (GBM + GBN) * GLD + GBM * GLD; };
    auto getAB = [&](int it, const __half*& A, const __half*& B, int& kt) {
        int seg = it / 12;
        kt = (it % 12) * GBK;
        A = seg ? Al : Ah;
        B = Bh;
    };

    {
        const __half *A, *B;
        int kt;
        getAB(0, A, B, kt);
        gemm_stage_load(stA(0), stB(0), A, B, m0, n0, kt, tid);
    }

#pragma unroll 1
    for (int it = 0; it < NIT; it++) {
        asm volatile("cp.async.wait_group 0;");
        __syncthreads();   // loads visible; prior compute on other buffer done

        if (it + 1 < NIT) {
            const __half *A, *B;
            int kt;
            getAB(it + 1, A, B, kt);
            gemm_stage_load(stA((it + 1) & 1), stB((it + 1) & 1), A, B, m0, n0,
                            kt, tid);
        }

        const __half* As = stA(it & 1);
        const __half* Bs = stB(it & 1);
#pragma unroll
        for (int kk = 0; kk < GBK; kk += 16) {
            wmma::fragment<wmma::matrix_a, 16, 16, 16, __half,
                           wmma::row_major> a0, a1;
            wmma::fragment<wmma::matrix_b, 16, 16, 16, __half,
                           wmma::col_major> b0, b1;
            wmma::load_matrix_sync(a0, &As[(wm * 32) * GLD + kk], GLD);
            wmma::load_matrix_sync(a1, &As[(wm * 32 + 16) * GLD + kk], GLD);
            wmma::load_matrix_sync(b0, &Bs[(wn * 32) * GLD + kk], GLD);
            wmma::load_matrix_sync(b1, &Bs[(wn * 32 + 16) * GLD + kk], GLD);
            wmma::mma_sync(acc[0][0], a0, b0, acc[0][0]);
            wmma::mma_sync(acc[0][1], a0, b1, acc[0][1]);
            wmma::mma_sync(acc[1][0], a1, b0, acc[1][0]);
            wmma::mma_sync(acc[1][1], a1, b1, acc[1][1]);
        }
    }

#pragma unroll
    for (int i = 0; i < 2; i++)
#pragma unroll
        for (int j = 0; j < 2; j++)
            wmma::store_matrix_sync(
                &C[(size_t)(m0 + wm * 32 + i * 16) * Cld + cn0 + wn * 32 + j * 16],
                acc[i][j], Cld, wmma::mem_row_major);
}

// merged Q/K/V/U/gate projection: 49 n-blocks (48 qkvu + 1 gate)
__global__ void __launch_bounds__(256) gemm_qkvu_tc() {
    int bx = blockIdx.x;
    int m0 = blockIdx.y * GBM;
    if (bx < 48) {
        int nglob = bx * GBN;
        int z = nglob / D;
        int n0 = nglob % D;
        float* Cs[4] = {g_q, g_k, g_v, g_u};
        gemm_body(g_Xh, g_Xl, g_Wh + (size_t)z * D * D, Cs[z], m0, n0, D, n0);
    } else {
        gemm_body(g_Xh, g_Xl, g_Wgph, g_gatep, m0, 0, 64, 0);
    }
}

__global__ void __launch_bounds__(256) gemm_out_tc(float* __restrict__ out) {
    int n0 = blockIdx.x * GBN;
    gemm_body(g_lnh, g_lnl, g_Wh + (size_t)4 * D * D, out, blockIdx.y * GBM, n0,
              D, n0);
}

// ---------------- fused: RoPE+normalize (split-emit)  ||  chunked cumsum ----
#define ROPE_BLOCKS 1536   // LH warps / 8 warps per block (warp per (l,h))
#define CUMSUM_BLOCKS 384  // (D/8) channel-groups x 4 chunks

__global__ void __launch_bounds__(256) rope_cumsum_fused() {
    __shared__ float sm[32][9];
    const int bx = blockIdx.x;
    const int tid = threadIdx.x;

    if (bx < ROPE_BLOCKS) {
        int gw = bx * 8 + (tid >> 5);
        int lane = tid & 31;
        int l = gw / NH, h = gw % NH;
        int base = l * D + h * HD;
        int i0 = lane >> 1;
        const float LN1E4_32 = 0.28782313662425572f;
        float f0 = expf(-(float)i0 * LN1E4_32);
        float f1 = expf(-(float)(i0 + 16) * LN1E4_32);
        float a0 = (float)l * f0;
        float a1 = (float)l * f1;
        float c0 = cosf(a0), sn0 = sinf(a0);
        float c1 = cosf(a1), sn1 = sinf(a1);

        {
            float x0 = g_q[base + lane], x1 = g_q[base + lane + 32];
            float r0 = x0 * c0 - x1 * sn0;
            float r1 = x1 * c1 + x0 * sn1;
            float nn = r0 * r0 + r1 * r1;
#pragma unroll
            for (int o = 16; o; o >>= 1) nn += __shfl_xor_sync(0xffffffffu, nn, o);
            float inv = 1.f / fmaxf(sqrtf(nn), 1e-12f);
            split_store(g_qh, g_ql, base + lane, r0 * inv);
            split_store(g_qh, g_ql, base + lane + 32, r1 * inv);
        }
        {
            float x0 = g_k[base + lane], x1 = g_k[base + lane + 32];
            float r0 = x0 * c0 - x1 * sn0;
            float r1 = x1 * c1 + x0 * sn1;
            float nn = r0 * r0 + r1 * r1;
#pragma unroll
            for (int o = 16; o; o >>= 1) nn += __shfl_xor_sync(0xffffffffu, nn, o);
            float inv = 1.f / fmaxf(sqrtf(nn), 1e-12f);
            split_store(g_kh, g_kl, base + lane, r0 * inv);
            split_store(g_kh, g_kl, base + lane + 32, r1 * inv);
        }
        {
            split_store(g_vh, g_vl, base + lane, g_v[base + lane]);
            split_store(g_vh, g_vl, base + lane + 32, g_v[base + lane + 32]);
        }
    } else {
        int bc = bx - ROPE_BLOCKS;
        const int c0 = (bc % 96) * 8;
        const int base = (bc / 96) * 256;
        const int w = tid >> 5, lane = tid & 31;
        const int lr = tid >> 3, lc = tid & 7;
        float carry = 0.f;
#pragma unroll 1
        for (int l0 = base; l0 < base + 256; l0 += 32) {
            float vin = g_u[(l0 + lr) * D + c0 + lc];
            __syncthreads();
            sm[lr][lc] = vin;
            __syncthreads();
            float v = sm[lane][w];
#pragma unroll
            for (int o = 1; o < 32; o <<= 1) {
                float n = __shfl_up_sync(0xffffffffu, v, o);
                if (lane >= o) v += n;
            }
            v += carry;
            carry = __shfl_sync(0xffffffffu, v, 31);
            sm[lane][w] = v;
            __syncthreads();
            g_usum[(l0 + lr) * D + c0 + lc] = sm[lr][lc];
        }
        if (lane == 0) g_ct[(bc / 96) * D + c0 + w] = carry;
    }
}

// ---------------- s_i = -(1/sqrt(d)) * u . bar_u (inline chunk prefix) ------
__global__ void compute_s(const float* __restrict__ pmu,
                          const float* __restrict__ plt) {
    int gw = (blockIdx.x * blockDim.x + threadIdx.x) >> 5;
    int lane = threadIdx.x & 31;
    if (gw >= LH) return;
    int l = gw / NH, h = gw % NH;
    float lt = expf(fminf(fmaxf(plt[h], -50.f), 30.f));
    float t = (float)(l + 1);
    float inv_den = 1.f / (lt + t);
    int chunk = l >> 8;
    float acc = 0.f;
#pragma unroll
    for (int r = 0; r < 2; r++) {
        int i = lane + r * 32;
        int ch = h * HD + i;
        float off = 0.f;
        for (int c = 0; c < chunk; c++) off += g_ct[c * D + ch];
        float uu = g_u[l * D + ch];
        float us = g_usum[l * D + ch] + off;
        float bu = (lt * pmu[ch] + us) * inv_den;
        acc = fmaf(uu, bu, acc);
    }
#pragma unroll
    for (int o = 16; o; o >>= 1) acc += __shfl_xor_sync(0xffffffffu, acc, o);
    if (lane == 0) g_s[l * NH + h] = -acc * 0.125f;
}

// ---------------- per-head: max, scans, gate coefficients -------------------
__global__ void __launch_bounds__(1024) head_scan() {
    __shared__ float she[1024];
    __shared__ float shp[1024];
    const int h = blockIdx.x;
    const int l = threadIdx.x;
    float s = g_s[l * NH + h];
    she[l] = s;
    __syncthreads();
    for (int off = 512; off > 0; off >>= 1) {
        if (l < off) she[l] = fmaxf(she[l], she[l + off]);
        __syncthreads();
    }
    float smax = she[0];
    __syncthreads();
    float e = expf(s - smax);
    float ev = e, pv = s;
    she[l] = ev;
    shp[l] = pv;
    __syncthreads();
    for (int off = 1; off < 1024; off <<= 1) {
        float ae = 0.f, ap = 0.f;
        if (l >= off) { ae = she[l - off]; ap = shp[l - off]; }
        __syncthreads();
        ev += ae;
        pv += ap;
        she[l] = ev;
        shp[l] = pv;
        __syncthreads();
    }
    float g1 = g_gatep[l * 64 + h * 3 + 0];
    float gh = g_gatep[l * 64 + h * 3 + 1];
    float s1 = 1.f / (1.f + expf(-g1));
    float shg = 1.f / (1.f + expf(-gh));
    float t = (float)(l + 1);
    float a = shg / (ev + 1e-12f);
    float b = (s1 - shg) / t;
    float gm = -(b * pv + shg) / t;
    int o = l * NH + h;
    g_es[o] = e;
    g_al[o] = a;
    g_be[o] = b;
    g_ga[o] = gm;
}

// ---------------- tensor-core weighted causal attention + LayerNorm ---------
// smem: Qh Ql Kh Kl Vh Vl (6 x 64*72 fp16) + Sf (64*68 fp32); S^T reuses K.
#define ALD 72
#define SLD 68
#define ATTN_SMEM (6 * 64 * ALD * 2 + 64 * SLD * 4)   // 72704 bytes

__global__ void __launch_bounds__(256) attn_tc() {
    extern __shared__ __half ash[];
    __half* Qh = ash;
    __half* Ql = ash + 1 * 64 * ALD;
    __half* Kh = ash + 2 * 64 * ALD;
    __half* Kl = ash + 3 * 64 * ALD;
    __half* Vh = ash + 4 * 64 * ALD;
    __half* Vl = ash + 5 * 64 * ALD;
    __half* Sh = Kh;  // K dead after S = QK^T; reuse for S^T hi
    __half* Sl = Kl;  // and S^T lo
    float* Sf = (float*)(ash + 6 * 64 * ALD);
    __shared__ float cA[64], cB[64], cG[64], sES[64], sS[64];

    const int h = blockIdx.y;
    const int lt = 15 - blockIdx.x;
    const int l0 = lt * 64;
    const int tid = threadIdx.x;
    const int warp = tid >> 5;
    const int wm = warp >> 1, wn = warp & 1;

#pragma unroll
    for (int it = 0; it < 2; it++) {
        int idx = tid + it * 256;
        int r = idx >> 3, c = (idx & 7) * 8;
        *(uint4*)&Qh[r * ALD + c] = *(const uint4*)&g_qh[(l0 + r) * D + h * HD + c];
        *(uint4*)&Ql[r * ALD + c] = *(const uint4*)&g_ql[(l0 + r) * D + h * HD + c];
    }
    if (tid < 64) {
        cA[tid] = g_al[(l0 + tid) * NH + h];
        cB[tid] = g_be[(l0 + tid) * NH + h];
        cG[tid] = g_ga[(l0 + tid) * NH + h];
    }

    wmma::fragment<wmma::accumulator, 16, 16, 16, float> acc_o[2];
    wmma::fill_fragment(acc_o[0], 0.f);
    wmma::fill_fragment(acc_o[1], 0.f);

    const int r_ = tid >> 2;
    const int cb_ = (tid & 3) * 16;

#pragma unroll 1
    for (int jt = 0; jt <= lt; jt++) {
        const int j0 = jt * 64;
        __syncthreads();   // prev O-mma done (S^T in K buffers now dead)
#pragma unroll
        for (int it = 0; it < 2; it++) {
            int idx = tid + it * 256;
            int r = idx >> 3, c = (idx & 7) * 8;
            *(uint4*)&Kh[r * ALD + c] = *(const uint4*)&g_kh[(j0 + r) * D + h * HD + c];
            *(uint4*)&Kl[r * ALD + c] = *(const uint4*)&g_kl[(j0 + r) * D + h * HD + c];
            *(uint4*)&Vh[r * ALD + c] = *(const uint4*)&g_vh[(j0 + r) * D + h * HD + c];
            *(uint4*)&Vl[r * ALD + c] = *(const uint4*)&g_vl[(j0 + r) * D + h * HD + c];
        }
        if (tid < 64) {
            sES[tid] = g_es[(j0 + tid) * NH + h];
            sS[tid] = g_s[(j0 + tid) * NH + h];
        }
        __syncthreads();

        wmma::fragment<wmma::accumulator, 16, 16, 16, float> acc_s[2];
        wmma::fill_fragment(acc_s[0], 0.f);
        wmma::fill_fragment(acc_s[1], 0.f);
#pragma unroll
        for (int p = 0; p < 3; p++) {
            const __half* Aq = (p == 1) ? Ql : Qh;
            const __half* Bk = (p == 2) ? Kl : Kh;
#pragma unroll
            for (int kk = 0; kk < 64; kk += 16) {
                wmma::fragment<wmma::matrix_a, 16, 16, 16, __half,
                               wmma::row_major> af;
                wmma::load_matrix_sync(af, &Aq[(wm * 16) * ALD + kk], ALD);
#pragma unroll
                for (int jn = 0; jn < 2; jn++) {
                    wmma::fragment<wmma::matrix_b, 16, 16, 16, __half,
                                   wmma::col_major> bf;
                    wmma::load_matrix_sync(
                        bf, &Bk[(wn * 32 + jn * 16) * ALD + kk], ALD);
                    wmma::mma_sync(acc_s[jn], af, bf, acc_s[jn]);
                }
            }
        }
#pragma unroll
        for (int jn = 0; jn < 2; jn++)
            wmma::store_matrix_sync(&Sf[(wm * 16) * SLD + wn * 32 + jn * 16],
                                    acc_s[jn], SLD, wmma::mem_row_major);
        __syncthreads();  // all S-mma done -> K buffers dead

        {
            float Ar = cA[r_], Br = cB[r_], Gr = cG[r_];
            int gl = l0 + r_;
#pragma unroll
            for (int i = 0; i < 16; i++) {
                int c = cb_ + i;
                float w = Ar * sES[c] + Br * sS[c] + Gr;
                float sv = (j0 + c <= gl) ? Sf[r_ * SLD + c] * w : 0.f;
                __half hb = __float2half_rn(sv);
                Sh[r_ * ALD + c] = hb;
                Sl[r_ * ALD + c] = __float2half_rn(sv - __half2float(hb));
            }
        }
        __syncthreads();

#pragma unroll
        for (int p = 0; p < 3; p++) {
            const __half* Asm = (p == 1) ? Sl : Sh;
            const __half* Bvm = (p == 2) ? Vl : Vh;
#pragma unroll
            for (int kk = 0; kk < 64; kk += 16) {
                wmma::fragment<wmma::matrix_a, 16, 16, 16, __half,
                               wmma::row_major> af;
                wmma::load_matrix_sync(af, &Asm[(wm * 16) * ALD + kk], ALD);
#pragma unroll
                for (int jn = 0; jn < 2; jn++) {
                    wmma::fragment<wmma::matrix_b, 16, 16, 16, __half,
                                   wmma::row_major> bf;
                    wmma::load_matrix_sync(bf, &Bvm[kk * ALD + wn * 32 + jn * 16],
                                           ALD);
                    wmma::mma_sync(acc_o[jn], af, bf, acc_o[jn]);
                }
            }
        }
    }

    __syncthreads();
#pragma unroll
    for (int jn = 0; jn < 2; jn++)
        wmma::store_matrix_sync(&Sf[(wm * 16) * SLD + wn * 32 + jn * 16],
                                acc_o[jn], SLD, wmma::mem_row_major);
    __syncthreads();
    {
        float vals[16];
        float sum = 0.f;
#pragma unroll
        for (int i = 0; i < 16; i++) {
            vals[i] = Sf[r_ * SLD + cb_ + i];
            sum += vals[i];
        }
        sum += __shfl_xor_sync(0xffffffffu, sum, 1);
        sum += __shfl_xor_sync(0xffffffffu, sum, 2);
        float mean = sum * (1.f / 64.f);
        float vs = 0.f;
#pragma unroll
        for (int i = 0; i < 16; i++) {
            vals[i] -= mean;
            vs += vals[i] * vals[i];
        }
        vs += __shfl_xor_sync(0xffffffffu, vs, 1);
        vs += __shfl_xor_sync(0xffffffffu, vs, 2);
        float inv = rsqrtf(vs * (1.f / 64.f) + 1e-5f);
        int off = (l0 + r_) * D + h * HD + cb_;
#pragma unroll
        for (int i = 0; i < 16; i += 2) {
            float v0 = vals[i] * inv, v1 = vals[i + 1] * inv;
            __half h0 = __float2half_rn(v0);
            __half h1 = __float2half_rn(v1);
            *(__half2*)&g_lnh[off + i] = __halves2half2(h0, h1);
            *(__half2*)&g_lnl[off + i] = __halves2half2(
                __float2half_rn(v0 - __half2float(h0)),
                __float2half_rn(v1 - __half2float(h1)));
        }
    }
}

// ---------------- launch ----------------------------------------------------
extern "C" void kernel_launch(void* const* d_in, const int* in_sizes, int n_in,
                              void* d_out, int out_size) {
    const float* X = (const float*)d_in[0];
    const float* Wq = (const float*)d_in[1];
    const float* Wk = (const float*)d_in[2];
    const float* Wv = (const float*)d_in[3];
    const float* Wu = (const float*)d_in[4];
    const float* Wg = (const float*)d_in[5];
    const float* Wo = (const float*)d_in[6];
    const float* pmu = (const float*)d_in[7];
    const float* plt = (const float*)d_in[8];
    float* out = (float*)d_out;

    cudaFuncSetAttribute(attn_tc, cudaFuncAttributeMaxDynamicSharedMemorySize,
                         ATTN_SMEM);
    cudaFuncSetAttribute(gemm_qkvu_tc, cudaFuncAttributeMaxDynamicSharedMemorySize,
                         GEMM_SMEM);
    cudaFuncSetAttribute(gemm_out_tc, cudaFuncAttributeMaxDynamicSharedMemorySize,
                         GEMM_SMEM);

    convert_inputs<<<dim3(96, 7), 256>>>(X, Wq, Wk, Wv, Wu, Wo, Wg);

    // merged Q/K/V/U + gate projection (2-pass split-fp16, 49 n-blocks)
    gemm_qkvu_tc<<<dim3(49, L / GBM), 256, GEMM_SMEM>>>();

    // fused RoPE/normalize (q,k,v) + chunked cumsum
    rope_cumsum_fused<<<ROPE_BLOCKS + CUMSUM_BLOCKS, 256>>>();

    compute_s<<<(LH * 32 + 255) / 256, 256>>>(pmu, plt);
    head_scan<<<NH, 1024>>>();

    attn_tc<<<dim3(16, NH), 256, ATTN_SMEM>>>();

    gemm_out_tc<<<dim3(D / GBN, L / GBM), 256, GEMM_SMEM>>>(out);
}